// round 4
// baseline (speedup 1.0000x reference)
#include <cuda_runtime.h>
#include <cstdint>
#include <math.h>

// Problem constants
#define B_ROWS   262144
#define F_DIM    128
#define N_TOTAL  33554432u   // B_ROWS * F_DIM
#define STEPS    10

// Global scratch (no cudaMalloc allowed)
__device__ double g_sum;
__device__ float  g_noise_scale;

// ---------------------------------------------------------------------------
// Threefry-2x32, 20 rounds (exact JAX/Random123 algorithm)
// ---------------------------------------------------------------------------
__host__ __device__ __forceinline__ void threefry2x32_20(
    uint32_t k0, uint32_t k1, uint32_t x0, uint32_t x1,
    uint32_t& o0, uint32_t& o1)
{
    uint32_t ks0 = k0, ks1 = k1, ks2 = k0 ^ k1 ^ 0x1BD11BDAu;
    x0 += ks0; x1 += ks1;
#define TF_R(r) { x0 += x1; x1 = (x1 << (r)) | (x1 >> (32 - (r))); x1 ^= x0; }
    TF_R(13) TF_R(15) TF_R(26) TF_R(6)
    x0 += ks1; x1 += ks2 + 1u;
    TF_R(17) TF_R(29) TF_R(16) TF_R(24)
    x0 += ks2; x1 += ks0 + 2u;
    TF_R(13) TF_R(15) TF_R(26) TF_R(6)
    x0 += ks0; x1 += ks1 + 3u;
    TF_R(17) TF_R(29) TF_R(16) TF_R(24)
    x0 += ks1; x1 += ks2 + 4u;
    TF_R(13) TF_R(15) TF_R(26) TF_R(6)
    x0 += ks2; x1 += ks0 + 5u;
#undef TF_R
    o0 = x0; o1 = x1;
}

// Partitionable 32-bit random bits for element idx (idx < 2^32):
// counter = (0, idx); bits = o0 ^ o1.
__device__ __forceinline__ uint32_t random_bits_part(
    uint32_t k0, uint32_t k1, uint32_t idx)
{
    uint32_t o0, o1;
    threefry2x32_20(k0, k1, 0u, idx, o0, o1);
    return o0 ^ o1;
}

// ---------------------------------------------------------------------------
// bits -> standard normal, matching JAX:
//   u = bitcast(bits>>9 | 0x3f800000) - 1          in [0,1)
//   v = max(lo, u*2 + lo), lo = nextafter(-1,0)
//   n = sqrt(2) * erfinv(v)   (XLA/Giles polynomial, w = -log1p(-v^2))
// ---------------------------------------------------------------------------
__device__ __forceinline__ float bits_to_normal(uint32_t bits)
{
    const float lo = -0.99999994f;
    float u = __uint_as_float((bits >> 9) | 0x3f800000u) - 1.0f;
    float x = fmaf(u, 2.0f, lo);
    x = fmaxf(x, lo);

    float w = -log1pf(-x * x);
    float p;
    if (w < 5.0f) {
        w -= 2.5f;
        p = 2.81022636e-08f;
        p = fmaf(p, w, 3.43273939e-07f);
        p = fmaf(p, w, -3.5233877e-06f);
        p = fmaf(p, w, -4.39150654e-06f);
        p = fmaf(p, w, 0.00021858087f);
        p = fmaf(p, w, -0.00125372503f);
        p = fmaf(p, w, -0.00417768164f);
        p = fmaf(p, w, 0.246640727f);
        p = fmaf(p, w, 1.50140941f);
    } else {
        w = sqrtf(w) - 3.0f;
        p = -0.000200214257f;
        p = fmaf(p, w, 0.000100950558f);
        p = fmaf(p, w, 0.00134934322f);
        p = fmaf(p, w, -0.00367342844f);
        p = fmaf(p, w, 0.00573950773f);
        p = fmaf(p, w, -0.0076224613f);
        p = fmaf(p, w, 0.00943887047f);
        p = fmaf(p, w, 1.00167406f);
        p = fmaf(p, w, 2.83297682f);
    }
    return 1.41421354f * (p * x);   // sqrt(2) * erfinv
}

// ---------------------------------------------------------------------------
// Kernel Z: zero the reduction accumulator
// ---------------------------------------------------------------------------
__global__ void zero_kernel() { g_sum = 0.0; }

// ---------------------------------------------------------------------------
// Phase 1: sum of (x - tanh(x @ W))^2 over all elements.
// One warp per row; lane owns cols 4*lane..4*lane+3; W staged in SMEM.
// ---------------------------------------------------------------------------
__global__ void __launch_bounds__(256) phase1_kernel(
    const float* __restrict__ x_input, const float* __restrict__ W)
{
    extern __shared__ float4 sW4[];   // 128 rows * 32 float4 = 64 KB
    int tid = threadIdx.x;
    for (int i = tid; i < 128 * 32; i += blockDim.x)
        sW4[i] = ((const float4*)W)[i];
    __syncthreads();

    int lane   = tid & 31;
    int warp   = tid >> 5;
    int gwarp  = blockIdx.x * (blockDim.x >> 5) + warp;
    int nwarps = gridDim.x * (blockDim.x >> 5);

    double acc = 0.0;
    for (int b = gwarp; b < B_ROWS; b += nwarps) {
        float4 t = ((const float4*)(x_input + (size_t)b * 128))[lane];
        float xin[4] = {t.x, t.y, t.z, t.w};
        float g[4] = {0.f, 0.f, 0.f, 0.f};
        for (int k4 = 0; k4 < 32; k4++) {
#pragma unroll
            for (int r = 0; r < 4; r++) {
                float xk = __shfl_sync(0xffffffffu, xin[r], k4);
                float4 w4 = sW4[(k4 * 4 + r) * 32 + lane];
                g[0] = fmaf(xk, w4.x, g[0]);
                g[1] = fmaf(xk, w4.y, g[1]);
                g[2] = fmaf(xk, w4.z, g[2]);
                g[3] = fmaf(xk, w4.w, g[3]);
            }
        }
        float local = 0.f;
#pragma unroll
        for (int r = 0; r < 4; r++) {
            float e = xin[r] - tanhf(g[r]);
            local = fmaf(e, e, local);
        }
        acc += (double)local;
    }
    // warp reduce
#pragma unroll
    for (int off = 16; off; off >>= 1)
        acc += __shfl_xor_sync(0xffffffffu, acc, off);
    __shared__ double sacc[8];
    if (lane == 0) sacc[warp] = acc;
    __syncthreads();
    if (tid == 0) {
        double t = 0.0;
#pragma unroll
        for (int i = 0; i < 8; i++) t += sacc[i];
        atomicAdd(&g_sum, t);
    }
}

// ---------------------------------------------------------------------------
// Kernel F: scalar -> noise scale
// ---------------------------------------------------------------------------
__global__ void finalize_kernel()
{
    double mean = g_sum * (1.0 / (double)N_TOTAL);
    float temp = 0.1f * (1.0f + (float)mean * 10.0f);
    g_noise_scale = sqrtf(2.0f * 0.1f * temp);
}

// ---------------------------------------------------------------------------
// Phase 2: fused 10-step Langevin. Two rows per warp: rows (p, p + B/2)
// (pairing amortizes the shared J SMEM reads and shuffles; PRNG is per
// element regardless).
//
// PRNG: jax_threefry_partitionable = True (modern default):
//   noise element idx <- bits = o0 ^ o1 of threefry(key_s, (0, idx)),
//   idx row-major over [B, F].
// ---------------------------------------------------------------------------
struct Keys { uint32_t k0[STEPS]; uint32_t k1[STEPS]; };

__global__ void __launch_bounds__(256) langevin_kernel(
    const float* __restrict__ x_input,
    const float* __restrict__ J,
    const float* __restrict__ h,
    float* __restrict__ out,
    Keys keys)
{
    extern __shared__ float4 sJ4[];   // 64 KB
    int tid = threadIdx.x;
    for (int i = tid; i < 128 * 32; i += blockDim.x)
        sJ4[i] = ((const float4*)J)[i];
    __syncthreads();

    float nscale = g_noise_scale;
    int lane   = tid & 31;
    int warp   = tid >> 5;
    int gwarp  = blockIdx.x * (blockDim.x >> 5) + warp;
    int nwarps = gridDim.x * (blockDim.x >> 5);

    float4 h4 = ((const float4*)h)[lane];
    float hr[4] = {h4.x, h4.y, h4.z, h4.w};

    const int PAIRS = B_ROWS / 2;
    for (int p = gwarp; p < PAIRS; p += nwarps) {
        int b0 = p, b1 = p + PAIRS;
        float4 t0 = ((const float4*)(x_input + (size_t)b0 * 128))[lane];
        float4 t1 = ((const float4*)(x_input + (size_t)b1 * 128))[lane];
        float xin0[4] = {t0.x, t0.y, t0.z, t0.w};
        float xin1[4] = {t1.x, t1.y, t1.z, t1.w};
        float x0r[4] = {0.f, 0.f, 0.f, 0.f};
        float x1r[4] = {0.f, 0.f, 0.f, 0.f};
        uint32_t base0 = (uint32_t)b0 * 128u + 4u * (uint32_t)lane;
        uint32_t base1 = (uint32_t)b1 * 128u + 4u * (uint32_t)lane;

        for (int s = 0; s < STEPS; s++) {
            uint32_t kk0 = keys.k0[s], kk1 = keys.k1[s];
            float g0[4] = {0.f, 0.f, 0.f, 0.f};
            float g1[4] = {0.f, 0.f, 0.f, 0.f};
            if (s != 0) {   // x == 0 at step 0 -> matvec is zero
                for (int k4 = 0; k4 < 32; k4++) {
#pragma unroll
                    for (int r = 0; r < 4; r++) {
                        float a0 = __shfl_sync(0xffffffffu, x0r[r], k4);
                        float a1 = __shfl_sync(0xffffffffu, x1r[r], k4);
                        float4 j4 = sJ4[(k4 * 4 + r) * 32 + lane];
                        g0[0] = fmaf(a0, j4.x, g0[0]);
                        g0[1] = fmaf(a0, j4.y, g0[1]);
                        g0[2] = fmaf(a0, j4.z, g0[2]);
                        g0[3] = fmaf(a0, j4.w, g0[3]);
                        g1[0] = fmaf(a1, j4.x, g1[0]);
                        g1[1] = fmaf(a1, j4.y, g1[1]);
                        g1[2] = fmaf(a1, j4.z, g1[2]);
                        g1[3] = fmaf(a1, j4.w, g1[3]);
                    }
                }
            }
#pragma unroll
            for (int r = 0; r < 4; r++) {
                uint32_t bits0 = random_bits_part(kk0, kk1, base0 + (uint32_t)r);
                uint32_t bits1 = random_bits_part(kk0, kk1, base1 + (uint32_t)r);
                float n0 = nscale * bits_to_normal(bits0);
                float n1 = nscale * bits_to_normal(bits1);
                float grad0 = g0[r] + hr[r] - xin0[r];
                float grad1 = g1[r] + hr[r] - xin1[r];
                x0r[r] = tanhf(fmaf(grad0, -0.1f, x0r[r]) + n0);
                x1r[r] = tanhf(fmaf(grad1, -0.1f, x1r[r]) + n1);
            }
        }
        float4 w0 = make_float4(x0r[0], x0r[1], x0r[2], x0r[3]);
        float4 w1 = make_float4(x1r[0], x1r[1], x1r[2], x1r[3]);
        ((float4*)(out + (size_t)b0 * 128))[lane] = w0;
        ((float4*)(out + (size_t)b1 * 128))[lane] = w1;
    }
}

// ---------------------------------------------------------------------------
// Launch
// ---------------------------------------------------------------------------
extern "C" void kernel_launch(void* const* d_in, const int* in_sizes, int n_in,
                              void* d_out, int out_size)
{
    const float* x_input = (const float*)d_in[0];
    const float* W       = (const float*)d_in[1];
    const float* J       = (const float*)d_in[2];
    const float* h       = (const float*)d_in[3];
    float* out           = (float*)d_out;

    // Foldlike split (partitionable): key_s = (o0, o1) of threefry((0,1),(0,s))
    Keys keys;
    for (int s = 0; s < STEPS; s++) {
        uint32_t o0, o1;
        threefry2x32_20(0u, 1u, 0u, (uint32_t)s, o0, o1);
        keys.k0[s] = o0;
        keys.k1[s] = o1;
    }

    const int SMEM = 128 * 128 * sizeof(float);   // 64 KB
    static bool attr_set = false;
    if (!attr_set) {
        cudaFuncSetAttribute(phase1_kernel,
            cudaFuncAttributeMaxDynamicSharedMemorySize, SMEM);
        cudaFuncSetAttribute(langevin_kernel,
            cudaFuncAttributeMaxDynamicSharedMemorySize, SMEM);
        attr_set = true;
    }

    zero_kernel<<<1, 1>>>();
    phase1_kernel<<<2048, 256, SMEM>>>(x_input, W);
    finalize_kernel<<<1, 1>>>();
    langevin_kernel<<<2048, 256, SMEM>>>(x_input, J, h, out, keys);
}

// round 6
// speedup vs baseline: 1.2400x; 1.2400x over previous
#include <cuda_runtime.h>
#include <cstdint>
#include <math.h>

#define B_ROWS   262144
#define STEPS    10
#define NTHREADS 256
#define N_TILES  2048          // B_ROWS / 128

__device__ double g_sum;
__device__ float  g_noise_scale;

// ---- SMEM layouts (word offsets) ----
#define XT_ROW 164   // tf32 X buffer: row stride (words); 4 classes * 40
#define XT_CLS 40
#define PL_ROW 132   // plain fp32 buffers row stride

#define LG_XT   0
#define LG_XEX  (128*XT_ROW)
#define LG_C    (LG_XEX + 128*PL_ROW)
#define LG_SMEM ((LG_C + 128*PL_ROW)*4)

#define P1_XT 0
#define P1_ST (128*XT_ROW)
#define P1_SMEM ((P1_ST + 128*PL_ROW)*4)

// ---------------------------------------------------------------------------
// mma.sync m16n8k8 tf32 helpers (legacy tensor path; works on plain sm_100)
// ---------------------------------------------------------------------------
__device__ __forceinline__ uint32_t f2tf32(float f) {
    uint32_t r;
    asm("cvt.rna.tf32.f32 %0, %1;" : "=r"(r) : "f"(f));
    return r;
}
__device__ __forceinline__ void mma_tf32(float d[4], const uint32_t a[4],
                                         const uint32_t b[2]) {
    asm volatile(
        "mma.sync.aligned.m16n8k8.row.col.f32.tf32.tf32.f32 "
        "{%0,%1,%2,%3}, {%4,%5,%6,%7}, {%8,%9}, {%0,%1,%2,%3};\n"
        : "+f"(d[0]), "+f"(d[1]), "+f"(d[2]), "+f"(d[3])
        : "r"(a[0]), "r"(a[1]), "r"(a[2]), "r"(a[3]), "r"(b[0]), "r"(b[1]));
}

// ---------------------------------------------------------------------------
// Threefry-2x32/20 (exact JAX); partitionable bits = o0 ^ o1 (round-4 PASS)
// ---------------------------------------------------------------------------
__host__ __device__ __forceinline__ void threefry2x32_20(
    uint32_t k0, uint32_t k1, uint32_t x0, uint32_t x1,
    uint32_t& o0, uint32_t& o1)
{
    uint32_t ks0 = k0, ks1 = k1, ks2 = k0 ^ k1 ^ 0x1BD11BDAu;
    x0 += ks0; x1 += ks1;
#define TF_R(r) { x0 += x1; x1 = (x1 << (r)) | (x1 >> (32 - (r))); x1 ^= x0; }
    TF_R(13) TF_R(15) TF_R(26) TF_R(6)
    x0 += ks1; x1 += ks2 + 1u;
    TF_R(17) TF_R(29) TF_R(16) TF_R(24)
    x0 += ks2; x1 += ks0 + 2u;
    TF_R(13) TF_R(15) TF_R(26) TF_R(6)
    x0 += ks0; x1 += ks1 + 3u;
    TF_R(17) TF_R(29) TF_R(16) TF_R(24)
    x0 += ks1; x1 += ks2 + 4u;
    TF_R(13) TF_R(15) TF_R(26) TF_R(6)
    x0 += ks2; x1 += ks0 + 5u;
#undef TF_R
    o0 = x0; o1 = x1;
}
__device__ __forceinline__ uint32_t rnd_bits(uint32_t k0, uint32_t k1, uint32_t idx) {
    uint32_t o0, o1;
    threefry2x32_20(k0, k1, 0u, idx, o0, o1);
    return o0 ^ o1;
}
__device__ __forceinline__ float bits_to_normal(uint32_t bits)
{
    const float lo = -0.99999994f;
    float u = __uint_as_float((bits >> 9) | 0x3f800000u) - 1.0f;
    float x = fmaf(u, 2.0f, lo);
    x = fmaxf(x, lo);
    float w = -log1pf(-x * x);
    float p;
    if (w < 5.0f) {
        w -= 2.5f;
        p = 2.81022636e-08f;
        p = fmaf(p, w, 3.43273939e-07f);
        p = fmaf(p, w, -3.5233877e-06f);
        p = fmaf(p, w, -4.39150654e-06f);
        p = fmaf(p, w, 0.00021858087f);
        p = fmaf(p, w, -0.00125372503f);
        p = fmaf(p, w, -0.00417768164f);
        p = fmaf(p, w, 0.246640727f);
        p = fmaf(p, w, 1.50140941f);
    } else {
        w = sqrtf(w) - 3.0f;
        p = -0.000200214257f;
        p = fmaf(p, w, 0.000100950558f);
        p = fmaf(p, w, 0.00134934322f);
        p = fmaf(p, w, -0.00367342844f);
        p = fmaf(p, w, 0.00573950773f);
        p = fmaf(p, w, -0.0076224613f);
        p = fmaf(p, w, 0.00943887047f);
        p = fmaf(p, w, 1.00167406f);
        p = fmaf(p, w, 2.83297682f);
    }
    return 1.41421354f * (p * x);
}

struct Keys { uint32_t k0[STEPS]; uint32_t k1[STEPS]; };

__global__ void zero_kernel() { g_sum = 0.0; }
__global__ void finalize_kernel()
{
    double mean = g_sum * (1.0 / 33554432.0);
    float temp = 0.1f * (1.0f + (float)mean * 10.0f);
    g_noise_scale = sqrtf(2.0f * 0.1f * temp);
}

// elementwise pair: x' = tanh((x + C) - 0.1*d + noise)
__device__ __forceinline__ float2 elw2(float d0, float d1, float2 xo, float2 cc,
    uint32_t row_g, uint32_t col0, uint32_t kk0, uint32_t kk1, float nscale)
{
    uint32_t base = row_g * 128u + col0;
    float n0 = nscale * bits_to_normal(rnd_bits(kk0, kk1, base));
    float n1 = nscale * bits_to_normal(rnd_bits(kk0, kk1, base + 1u));
    float2 r;
    r.x = tanhf(fmaf(d0, -0.1f, xo.x + cc.x) + n0);
    r.y = tanhf(fmaf(d1, -0.1f, xo.y + cc.y) + n1);
    return r;
}

// ===========================================================================
// Phase 1: free energy via mma.sync
// ===========================================================================
__global__ void __launch_bounds__(NTHREADS, 1) phase1_mma(
    const float* __restrict__ x_input, const float* __restrict__ W)
{
    extern __shared__ float sm[];
    uint32_t* smu = (uint32_t*)sm;
    int tid = threadIdx.x, w = tid >> 5, lane = tid & 31;
    int g = lane >> 2, i = lane & 3;
    int N0 = 16 * w;
    int tb = blockIdx.x * 128;

    // stage W (plain) into P1_ST
    const float4* W4 = (const float4*)W;
    for (int idx = tid; idx < 4096; idx += NTHREADS) {
        int r = idx >> 5, q = idx & 31;
        *(float4*)&sm[P1_ST + r * PL_ROW + 4 * q] = W4[idx];
    }
    __syncthreads();

    // persistent B fragments: b0 = W[8kk+i][N0+8j+g], b1 = W[8kk+i+4][...]
    uint32_t Bf[16][2][2];
#pragma unroll
    for (int kk = 0; kk < 16; kk++)
#pragma unroll
        for (int j = 0; j < 2; j++) {
            Bf[kk][j][0] = f2tf32(sm[P1_ST + (8 * kk + i) * PL_ROW + N0 + 8 * j + g]);
            Bf[kk][j][1] = f2tf32(sm[P1_ST + (8 * kk + i + 4) * PL_ROW + N0 + 8 * j + g]);
        }
    __syncthreads();

    // stage x tile: plain (P1_ST, overwrite W) + tf32 class layout (P1_XT)
    const float4* X4 = (const float4*)(x_input + (size_t)tb * 128);
    for (int idx = tid; idx < 4096; idx += NTHREADS) {
        int r = idx >> 5, q = idx & 31;
        float4 v = X4[idx];
        *(float4*)&sm[P1_ST + r * PL_ROW + 4 * q] = v;
        smu[P1_XT + r * XT_ROW + 0 * XT_CLS + q] = f2tf32(v.x);
        smu[P1_XT + r * XT_ROW + 1 * XT_CLS + q] = f2tf32(v.y);
        smu[P1_XT + r * XT_ROW + 2 * XT_CLS + q] = f2tf32(v.z);
        smu[P1_XT + r * XT_ROW + 3 * XT_CLS + q] = f2tf32(v.w);
    }
    __syncthreads();

    float acc = 0.f;
#pragma unroll 1
    for (int R = 0; R < 8; R++) {
        int r0 = 16 * R + g, r1 = r0 + 8;
        float D0[4] = {0,0,0,0}, D1[4] = {0,0,0,0};
        const uint32_t* xt0 = &smu[P1_XT + r0 * XT_ROW + i * XT_CLS];
        const uint32_t* xt1 = &smu[P1_XT + r1 * XT_ROW + i * XT_CLS];
#pragma unroll
        for (int j = 0; j < 8; j++) {
            uint4 va = *(const uint4*)(xt0 + 4 * j);
            uint4 vb = *(const uint4*)(xt1 + 4 * j);
            uint32_t a[4];
            a[0] = va.x; a[1] = vb.x; a[2] = va.y; a[3] = vb.y;
            mma_tf32(D0, a, Bf[2 * j][0]);
            mma_tf32(D1, a, Bf[2 * j][1]);
            a[0] = va.z; a[1] = vb.z; a[2] = va.w; a[3] = vb.w;
            mma_tf32(D0, a, Bf[2 * j + 1][0]);
            mma_tf32(D1, a, Bf[2 * j + 1][1]);
        }
        int cA = N0 + 2 * i, cB = cA + 8;
        float2 x00 = *(float2*)&sm[P1_ST + r0 * PL_ROW + cA];
        float2 x01 = *(float2*)&sm[P1_ST + r0 * PL_ROW + cB];
        float2 x10 = *(float2*)&sm[P1_ST + r1 * PL_ROW + cA];
        float2 x11 = *(float2*)&sm[P1_ST + r1 * PL_ROW + cB];
        float e;
        e = x00.x - tanhf(D0[0]); acc = fmaf(e, e, acc);
        e = x00.y - tanhf(D0[1]); acc = fmaf(e, e, acc);
        e = x01.x - tanhf(D1[0]); acc = fmaf(e, e, acc);
        e = x01.y - tanhf(D1[1]); acc = fmaf(e, e, acc);
        e = x10.x - tanhf(D0[2]); acc = fmaf(e, e, acc);
        e = x10.y - tanhf(D0[3]); acc = fmaf(e, e, acc);
        e = x11.x - tanhf(D1[2]); acc = fmaf(e, e, acc);
        e = x11.y - tanhf(D1[3]); acc = fmaf(e, e, acc);
    }
    double da = (double)acc;
#pragma unroll
    for (int off = 16; off; off >>= 1)
        da += __shfl_xor_sync(0xffffffffu, da, off);
    __shared__ double sacc[8];
    if (lane == 0) sacc[w] = da;
    __syncthreads();
    if (tid == 0) {
        double t = 0.0;
#pragma unroll
        for (int k = 0; k < 8; k++) t += sacc[k];
        atomicAdd(&g_sum, t);
    }
}

// ===========================================================================
// Langevin: 10 fused steps, matvec on mma.sync, J frags persistent in regs
// ===========================================================================
__global__ void __launch_bounds__(NTHREADS, 1) langevin_mma(
    const float* __restrict__ x_input, const float* __restrict__ J,
    const float* __restrict__ h, float* __restrict__ out, Keys keys)
{
    extern __shared__ float sm[];
    uint32_t* smu = (uint32_t*)sm;
    int tid = threadIdx.x, w = tid >> 5, lane = tid & 31;
    int g = lane >> 2, i = lane & 3;
    int N0 = 16 * w;
    int tb = blockIdx.x * 128;

    // stage J (plain) into LG_C region
    const float4* J4 = (const float4*)J;
    for (int idx = tid; idx < 4096; idx += NTHREADS) {
        int r = idx >> 5, q = idx & 31;
        *(float4*)&sm[LG_C + r * PL_ROW + 4 * q] = J4[idx];
    }
    __syncthreads();

    uint32_t Bf[16][2][2];
#pragma unroll
    for (int kk = 0; kk < 16; kk++)
#pragma unroll
        for (int j = 0; j < 2; j++) {
            Bf[kk][j][0] = f2tf32(sm[LG_C + (8 * kk + i) * PL_ROW + N0 + 8 * j + g]);
            Bf[kk][j][1] = f2tf32(sm[LG_C + (8 * kk + i + 4) * PL_ROW + N0 + 8 * j + g]);
        }
    __syncthreads();

    // C = 0.1*(xin - h), overwriting J staging
    const float4* X4 = (const float4*)(x_input + (size_t)tb * 128);
    const float4* H4 = (const float4*)h;
    for (int idx = tid; idx < 4096; idx += NTHREADS) {
        int r = idx >> 5, q = idx & 31;
        float4 v = X4[idx], hv = H4[q];
        float4 c;
        c.x = 0.1f * (v.x - hv.x);
        c.y = 0.1f * (v.y - hv.y);
        c.z = 0.1f * (v.z - hv.z);
        c.w = 0.1f * (v.w - hv.w);
        *(float4*)&sm[LG_C + r * PL_ROW + 4 * q] = c;
    }
    float nscale = g_noise_scale;
    __syncthreads();

    int cA = N0 + 2 * i, cB = cA + 8;

    // ---- step 0: x = 0, d = 0 ----
    {
        uint32_t kk0 = keys.k0[0], kk1 = keys.k1[0];
#pragma unroll 1
        for (int R = 0; R < 8; R++) {
            int r0 = 16 * R + g, r1 = r0 + 8;
            float2 z = make_float2(0.f, 0.f);
            float2 c00 = *(float2*)&sm[LG_C + r0 * PL_ROW + cA];
            float2 c01 = *(float2*)&sm[LG_C + r0 * PL_ROW + cB];
            float2 c10 = *(float2*)&sm[LG_C + r1 * PL_ROW + cA];
            float2 c11 = *(float2*)&sm[LG_C + r1 * PL_ROW + cB];
            float2 n00 = elw2(0.f, 0.f, z, c00, tb + r0, cA, kk0, kk1, nscale);
            float2 n01 = elw2(0.f, 0.f, z, c01, tb + r0, cB, kk0, kk1, nscale);
            float2 n10 = elw2(0.f, 0.f, z, c10, tb + r1, cA, kk0, kk1, nscale);
            float2 n11 = elw2(0.f, 0.f, z, c11, tb + r1, cB, kk0, kk1, nscale);
            *(float2*)&sm[LG_XEX + r0 * PL_ROW + cA] = n00;
            *(float2*)&sm[LG_XEX + r0 * PL_ROW + cB] = n01;
            *(float2*)&sm[LG_XEX + r1 * PL_ROW + cA] = n10;
            *(float2*)&sm[LG_XEX + r1 * PL_ROW + cB] = n11;
            smu[LG_XT + r0 * XT_ROW + (cA & 3) * XT_CLS + (cA >> 2)] = f2tf32(n00.x);
            smu[LG_XT + r0 * XT_ROW + ((cA+1) & 3) * XT_CLS + ((cA+1) >> 2)] = f2tf32(n00.y);
            smu[LG_XT + r0 * XT_ROW + (cB & 3) * XT_CLS + (cB >> 2)] = f2tf32(n01.x);
            smu[LG_XT + r0 * XT_ROW + ((cB+1) & 3) * XT_CLS + ((cB+1) >> 2)] = f2tf32(n01.y);
            smu[LG_XT + r1 * XT_ROW + (cA & 3) * XT_CLS + (cA >> 2)] = f2tf32(n10.x);
            smu[LG_XT + r1 * XT_ROW + ((cA+1) & 3) * XT_CLS + ((cA+1) >> 2)] = f2tf32(n10.y);
            smu[LG_XT + r1 * XT_ROW + (cB & 3) * XT_CLS + (cB >> 2)] = f2tf32(n11.x);
            smu[LG_XT + r1 * XT_ROW + ((cB+1) & 3) * XT_CLS + ((cB+1) >> 2)] = f2tf32(n11.y);
        }
    }

    // ---- steps 1..9 ----
    for (int s = 1; s < STEPS; s++) {
        uint32_t kk0 = keys.k0[s], kk1 = keys.k1[s];
        bool lastS = (s == STEPS - 1);
#pragma unroll 1
        for (int R = 0; R < 8; R++) {
            int r0 = 16 * R + g, r1 = r0 + 8;
            __syncthreads();   // bar_A: separates this chunk's XT reads from writes
            float D0[4] = {0,0,0,0}, D1[4] = {0,0,0,0};
            {
                const uint32_t* xt0 = &smu[LG_XT + r0 * XT_ROW + i * XT_CLS];
                const uint32_t* xt1 = &smu[LG_XT + r1 * XT_ROW + i * XT_CLS];
#pragma unroll
                for (int j = 0; j < 8; j++) {
                    uint4 va = *(const uint4*)(xt0 + 4 * j);
                    uint4 vb = *(const uint4*)(xt1 + 4 * j);
                    uint32_t a[4];
                    a[0] = va.x; a[1] = vb.x; a[2] = va.y; a[3] = vb.y;
                    mma_tf32(D0, a, Bf[2 * j][0]);
                    mma_tf32(D1, a, Bf[2 * j][1]);
                    a[0] = va.z; a[1] = vb.z; a[2] = va.w; a[3] = vb.w;
                    mma_tf32(D0, a, Bf[2 * j + 1][0]);
                    mma_tf32(D1, a, Bf[2 * j + 1][1]);
                }
            }
            float2 xo00 = *(float2*)&sm[LG_XEX + r0 * PL_ROW + cA];
            float2 xo01 = *(float2*)&sm[LG_XEX + r0 * PL_ROW + cB];
            float2 xo10 = *(float2*)&sm[LG_XEX + r1 * PL_ROW + cA];
            float2 xo11 = *(float2*)&sm[LG_XEX + r1 * PL_ROW + cB];
            float2 c00 = *(float2*)&sm[LG_C + r0 * PL_ROW + cA];
            float2 c01 = *(float2*)&sm[LG_C + r0 * PL_ROW + cB];
            float2 c10 = *(float2*)&sm[LG_C + r1 * PL_ROW + cA];
            float2 c11 = *(float2*)&sm[LG_C + r1 * PL_ROW + cB];
            float2 n00 = elw2(D0[0], D0[1], xo00, c00, tb + r0, cA, kk0, kk1, nscale);
            float2 n01 = elw2(D1[0], D1[1], xo01, c01, tb + r0, cB, kk0, kk1, nscale);
            float2 n10 = elw2(D0[2], D0[3], xo10, c10, tb + r1, cA, kk0, kk1, nscale);
            float2 n11 = elw2(D1[2], D1[3], xo11, c11, tb + r1, cB, kk0, kk1, nscale);
            __syncthreads();   // bar_B: all reads done -> safe to overwrite
            *(float2*)&sm[LG_XEX + r0 * PL_ROW + cA] = n00;
            *(float2*)&sm[LG_XEX + r0 * PL_ROW + cB] = n01;
            *(float2*)&sm[LG_XEX + r1 * PL_ROW + cA] = n10;
            *(float2*)&sm[LG_XEX + r1 * PL_ROW + cB] = n11;
            if (!lastS) {
                smu[LG_XT + r0 * XT_ROW + (cA & 3) * XT_CLS + (cA >> 2)] = f2tf32(n00.x);
                smu[LG_XT + r0 * XT_ROW + ((cA+1) & 3) * XT_CLS + ((cA+1) >> 2)] = f2tf32(n00.y);
                smu[LG_XT + r0 * XT_ROW + (cB & 3) * XT_CLS + (cB >> 2)] = f2tf32(n01.x);
                smu[LG_XT + r0 * XT_ROW + ((cB+1) & 3) * XT_CLS + ((cB+1) >> 2)] = f2tf32(n01.y);
                smu[LG_XT + r1 * XT_ROW + (cA & 3) * XT_CLS + (cA >> 2)] = f2tf32(n10.x);
                smu[LG_XT + r1 * XT_ROW + ((cA+1) & 3) * XT_CLS + ((cA+1) >> 2)] = f2tf32(n10.y);
                smu[LG_XT + r1 * XT_ROW + (cB & 3) * XT_CLS + (cB >> 2)] = f2tf32(n11.x);
                smu[LG_XT + r1 * XT_ROW + ((cB+1) & 3) * XT_CLS + ((cB+1) >> 2)] = f2tf32(n11.y);
            }
        }
    }
    __syncthreads();

    // output copy, coalesced
    float4* o4 = (float4*)(out + (size_t)tb * 128);
    for (int idx = tid; idx < 4096; idx += NTHREADS) {
        int r = idx >> 5, q = idx & 31;
        o4[idx] = *(float4*)&sm[LG_XEX + r * PL_ROW + 4 * q];
    }
}

// ===========================================================================
// Launch
// ===========================================================================
extern "C" void kernel_launch(void* const* d_in, const int* in_sizes, int n_in,
                              void* d_out, int out_size)
{
    const float* x_input = (const float*)d_in[0];
    const float* W       = (const float*)d_in[1];
    const float* J       = (const float*)d_in[2];
    const float* h       = (const float*)d_in[3];
    float* out           = (float*)d_out;

    Keys keys;
    for (int s = 0; s < STEPS; s++) {
        uint32_t o0, o1;
        threefry2x32_20(0u, 1u, 0u, (uint32_t)s, o0, o1);
        keys.k0[s] = o0;
        keys.k1[s] = o1;
    }

    static bool attr_set = false;
    if (!attr_set) {
        cudaFuncSetAttribute(phase1_mma,
            cudaFuncAttributeMaxDynamicSharedMemorySize, P1_SMEM);
        cudaFuncSetAttribute(langevin_mma,
            cudaFuncAttributeMaxDynamicSharedMemorySize, LG_SMEM);
        attr_set = true;
    }

    zero_kernel<<<1, 1>>>();
    phase1_mma<<<N_TILES, NTHREADS, P1_SMEM>>>(x_input, W);
    finalize_kernel<<<1, 1>>>();
    langevin_mma<<<N_TILES, NTHREADS, LG_SMEM>>>(x_input, J, h, out, keys);
}

// round 7
// speedup vs baseline: 1.8948x; 1.5281x over previous
#include <cuda_runtime.h>
#include <cstdint>
#include <math.h>

#define B_ROWS   262144
#define STEPS    10
#define NTHREADS 256

__device__ double g_sum;
__device__ float  g_noise_scale;

// ---- SMEM word-offset layouts (64-row tiles) ----
#define XT_ROW 164   // tf32 X: row stride (words) = 4 classes * 40 + pad
#define XT_CLS 40
#define PL_ROW 132   // plain fp32 row stride

// langevin: [XT 64*164 | XEX 64*132 | C 64*132] ; J staged over first 16896 words
#define LG_XT   0
#define LG_XEX  (64*XT_ROW)                 // 10496
#define LG_C    (LG_XEX + 64*PL_ROW)        // 18944
#define LG_WORDS (LG_C + 64*PL_ROW)         // 27392
#define LG_SMEM (LG_WORDS*4)                // 109568 B

// phase1: [XT 64*164 | XST 64*132] ; W staged over first 16896 words
#define P1_XT  0
#define P1_XST (64*XT_ROW)
#define P1_WORDS (P1_XST + 64*PL_ROW)       // 18944
#define P1_SMEM (P1_WORDS*4)                // 75776 B

// ---------------------------------------------------------------------------
// mma.sync m16n8k8 tf32 (legacy tensor path, plain sm_100-safe)
// ---------------------------------------------------------------------------
__device__ __forceinline__ uint32_t f2tf32(float f) {
    uint32_t r;
    asm("cvt.rna.tf32.f32 %0, %1;" : "=r"(r) : "f"(f));
    return r;
}
__device__ __forceinline__ void mma_tf32(float d[4], const uint32_t a[4],
                                         const uint32_t b[2]) {
    asm volatile(
        "mma.sync.aligned.m16n8k8.row.col.f32.tf32.tf32.f32 "
        "{%0,%1,%2,%3}, {%4,%5,%6,%7}, {%8,%9}, {%0,%1,%2,%3};\n"
        : "+f"(d[0]), "+f"(d[1]), "+f"(d[2]), "+f"(d[3])
        : "r"(a[0]), "r"(a[1]), "r"(a[2]), "r"(a[3]), "r"(b[0]), "r"(b[1]));
}

// ---------------------------------------------------------------------------
// Threefry-2x32/20 (exact JAX); partitionable bits = o0 ^ o1
// ---------------------------------------------------------------------------
__host__ __device__ __forceinline__ void threefry2x32_20(
    uint32_t k0, uint32_t k1, uint32_t x0, uint32_t x1,
    uint32_t& o0, uint32_t& o1)
{
    uint32_t ks0 = k0, ks1 = k1, ks2 = k0 ^ k1 ^ 0x1BD11BDAu;
    x0 += ks0; x1 += ks1;
#define TF_R(r) { x0 += x1; x1 = (x1 << (r)) | (x1 >> (32 - (r))); x1 ^= x0; }
    TF_R(13) TF_R(15) TF_R(26) TF_R(6)
    x0 += ks1; x1 += ks2 + 1u;
    TF_R(17) TF_R(29) TF_R(16) TF_R(24)
    x0 += ks2; x1 += ks0 + 2u;
    TF_R(13) TF_R(15) TF_R(26) TF_R(6)
    x0 += ks0; x1 += ks1 + 3u;
    TF_R(17) TF_R(29) TF_R(16) TF_R(24)
    x0 += ks1; x1 += ks2 + 4u;
    TF_R(13) TF_R(15) TF_R(26) TF_R(6)
    x0 += ks2; x1 += ks0 + 5u;
#undef TF_R
    o0 = x0; o1 = x1;
}
__device__ __forceinline__ uint32_t rnd_bits(uint32_t k0, uint32_t k1, uint32_t idx) {
    uint32_t o0, o1;
    threefry2x32_20(k0, k1, 0u, idx, o0, o1);
    return o0 ^ o1;
}
__device__ __forceinline__ float bits_to_normal(uint32_t bits)
{
    const float lo = -0.99999994f;
    float u = __uint_as_float((bits >> 9) | 0x3f800000u) - 1.0f;
    float x = fmaf(u, 2.0f, lo);
    x = fmaxf(x, lo);
    // w = -log1p(-x^2); fma keeps 1-x^2 single-rounded, __logf = MUFU.LG2 path
    float w = -__logf(fmaf(-x, x, 1.0f));
    float p;
    if (w < 5.0f) {
        w -= 2.5f;
        p = 2.81022636e-08f;
        p = fmaf(p, w, 3.43273939e-07f);
        p = fmaf(p, w, -3.5233877e-06f);
        p = fmaf(p, w, -4.39150654e-06f);
        p = fmaf(p, w, 0.00021858087f);
        p = fmaf(p, w, -0.00125372503f);
        p = fmaf(p, w, -0.00417768164f);
        p = fmaf(p, w, 0.246640727f);
        p = fmaf(p, w, 1.50140941f);
    } else {
        w = sqrtf(w) - 3.0f;
        p = -0.000200214257f;
        p = fmaf(p, w, 0.000100950558f);
        p = fmaf(p, w, 0.00134934322f);
        p = fmaf(p, w, -0.00367342844f);
        p = fmaf(p, w, 0.00573950773f);
        p = fmaf(p, w, -0.0076224613f);
        p = fmaf(p, w, 0.00943887047f);
        p = fmaf(p, w, 1.00167406f);
        p = fmaf(p, w, 2.83297682f);
    }
    return 1.41421354f * (p * x);
}

struct Keys { uint32_t k0[STEPS]; uint32_t k1[STEPS]; };

__global__ void zero_kernel() { g_sum = 0.0; }
__global__ void finalize_kernel()
{
    double mean = g_sum * (1.0 / 33554432.0);
    float temp = 0.1f * (1.0f + (float)mean * 10.0f);
    g_noise_scale = sqrtf(2.0f * 0.1f * temp);
}

__device__ __forceinline__ float2 elw2(float d0, float d1, float2 xo, float2 cc,
    uint32_t row_g, uint32_t col0, uint32_t kk0, uint32_t kk1, float nscale)
{
    uint32_t base = row_g * 128u + col0;
    float n0 = nscale * bits_to_normal(rnd_bits(kk0, kk1, base));
    float n1 = nscale * bits_to_normal(rnd_bits(kk0, kk1, base + 1u));
    float2 r;
    r.x = tanhf(fmaf(d0, -0.1f, xo.x + cc.x) + n0);
    r.y = tanhf(fmaf(d1, -0.1f, xo.y + cc.y) + n1);
    return r;
}

// ===========================================================================
// Phase 1: free energy via mma.sync, 64-row tiles, 2 CTAs/SM
// ===========================================================================
__global__ void __launch_bounds__(NTHREADS, 2) phase1_mma(
    const float* __restrict__ x_input, const float* __restrict__ W)
{
    extern __shared__ float sm[];
    uint32_t* smu = (uint32_t*)sm;
    int tid = threadIdx.x, w = tid >> 5, lane = tid & 31;
    int g = lane >> 2, i = lane & 3;
    int N0 = 16 * w;
    int tb = blockIdx.x * 64;

    // stage W [128x128] plain at offset 0 (row stride PL_ROW)
    const float4* W4 = (const float4*)W;
    for (int idx = tid; idx < 4096; idx += NTHREADS) {
        int r = idx >> 5, q = idx & 31;
        *(float4*)&sm[r * PL_ROW + 4 * q] = W4[idx];
    }
    __syncthreads();

    uint32_t Bf[16][2][2];
#pragma unroll
    for (int kk = 0; kk < 16; kk++)
#pragma unroll
        for (int j = 0; j < 2; j++) {
            Bf[kk][j][0] = f2tf32(sm[(8 * kk + i) * PL_ROW + N0 + 8 * j + g]);
            Bf[kk][j][1] = f2tf32(sm[(8 * kk + i + 4) * PL_ROW + N0 + 8 * j + g]);
        }
    __syncthreads();

    // stage x tile (64 rows): plain at P1_XST + tf32 class layout at P1_XT
    const float4* X4 = (const float4*)(x_input + (size_t)tb * 128);
    for (int idx = tid; idx < 2048; idx += NTHREADS) {
        int r = idx >> 5, q = idx & 31;
        float4 v = X4[idx];
        *(float4*)&sm[P1_XST + r * PL_ROW + 4 * q] = v;
        smu[P1_XT + r * XT_ROW + 0 * XT_CLS + q] = f2tf32(v.x);
        smu[P1_XT + r * XT_ROW + 1 * XT_CLS + q] = f2tf32(v.y);
        smu[P1_XT + r * XT_ROW + 2 * XT_CLS + q] = f2tf32(v.z);
        smu[P1_XT + r * XT_ROW + 3 * XT_CLS + q] = f2tf32(v.w);
    }
    __syncthreads();

    int cA = N0 + 2 * i, cB = cA + 8;
    float acc = 0.f;
#pragma unroll 1
    for (int R = 0; R < 4; R++) {
        int r0 = 16 * R + g, r1 = r0 + 8;
        float D0[4] = {0,0,0,0}, D1[4] = {0,0,0,0};
        const uint32_t* xt0 = &smu[P1_XT + r0 * XT_ROW + i * XT_CLS];
        const uint32_t* xt1 = &smu[P1_XT + r1 * XT_ROW + i * XT_CLS];
#pragma unroll
        for (int j = 0; j < 8; j++) {
            uint4 va = *(const uint4*)(xt0 + 4 * j);
            uint4 vb = *(const uint4*)(xt1 + 4 * j);
            uint32_t a[4];
            a[0] = va.x; a[1] = vb.x; a[2] = va.y; a[3] = vb.y;
            mma_tf32(D0, a, Bf[2 * j][0]);
            mma_tf32(D1, a, Bf[2 * j][1]);
            a[0] = va.z; a[1] = vb.z; a[2] = va.w; a[3] = vb.w;
            mma_tf32(D0, a, Bf[2 * j + 1][0]);
            mma_tf32(D1, a, Bf[2 * j + 1][1]);
        }
        float2 x00 = *(float2*)&sm[P1_XST + r0 * PL_ROW + cA];
        float2 x01 = *(float2*)&sm[P1_XST + r0 * PL_ROW + cB];
        float2 x10 = *(float2*)&sm[P1_XST + r1 * PL_ROW + cA];
        float2 x11 = *(float2*)&sm[P1_XST + r1 * PL_ROW + cB];
        float e;
        e = x00.x - tanhf(D0[0]); acc = fmaf(e, e, acc);
        e = x00.y - tanhf(D0[1]); acc = fmaf(e, e, acc);
        e = x01.x - tanhf(D1[0]); acc = fmaf(e, e, acc);
        e = x01.y - tanhf(D1[1]); acc = fmaf(e, e, acc);
        e = x10.x - tanhf(D0[2]); acc = fmaf(e, e, acc);
        e = x10.y - tanhf(D0[3]); acc = fmaf(e, e, acc);
        e = x11.x - tanhf(D1[2]); acc = fmaf(e, e, acc);
        e = x11.y - tanhf(D1[3]); acc = fmaf(e, e, acc);
    }
    double da = (double)acc;
#pragma unroll
    for (int off = 16; off; off >>= 1)
        da += __shfl_xor_sync(0xffffffffu, da, off);
    __shared__ double sacc[8];
    if (lane == 0) sacc[w] = da;
    __syncthreads();
    if (tid == 0) {
        double t = 0.0;
#pragma unroll
        for (int k = 0; k < 8; k++) t += sacc[k];
        atomicAdd(&g_sum, t);
    }
}

// ===========================================================================
// Langevin: 64-row tiles, 2 CTAs/SM, 2 barriers/step (pair-wise hazard proof)
// ===========================================================================
__global__ void __launch_bounds__(NTHREADS, 2) langevin_mma(
    const float* __restrict__ x_input, const float* __restrict__ J,
    const float* __restrict__ h, float* __restrict__ out, Keys keys)
{
    extern __shared__ float sm[];
    uint32_t* smu = (uint32_t*)sm;
    int tid = threadIdx.x, w = tid >> 5, lane = tid & 31;
    int g = lane >> 2, i = lane & 3;
    int N0 = 16 * w;
    int tb = blockIdx.x * 64;

    // stage J [128x128] plain at offset 0
    const float4* J4 = (const float4*)J;
    for (int idx = tid; idx < 4096; idx += NTHREADS) {
        int r = idx >> 5, q = idx & 31;
        *(float4*)&sm[r * PL_ROW + 4 * q] = J4[idx];
    }
    __syncthreads();

    uint32_t Bf[16][2][2];
#pragma unroll
    for (int kk = 0; kk < 16; kk++)
#pragma unroll
        for (int j = 0; j < 2; j++) {
            Bf[kk][j][0] = f2tf32(sm[(8 * kk + i) * PL_ROW + N0 + 8 * j + g]);
            Bf[kk][j][1] = f2tf32(sm[(8 * kk + i + 4) * PL_ROW + N0 + 8 * j + g]);
        }
    __syncthreads();

    // stage C = 0.1*(xin - h); XEX/XT written in step 0
    const float4* X4 = (const float4*)(x_input + (size_t)tb * 128);
    const float4* H4 = (const float4*)h;
    for (int idx = tid; idx < 2048; idx += NTHREADS) {
        int r = idx >> 5, q = idx & 31;
        float4 v = X4[idx], hv = H4[q];
        float4 c;
        c.x = 0.1f * (v.x - hv.x);
        c.y = 0.1f * (v.y - hv.y);
        c.z = 0.1f * (v.z - hv.z);
        c.w = 0.1f * (v.w - hv.w);
        *(float4*)&sm[LG_C + r * PL_ROW + 4 * q] = c;
    }
    float nscale = g_noise_scale;
    __syncthreads();

    int cA = N0 + 2 * i, cB = cA + 8;

    // ---- step 0: x = 0, d = 0 ----
    {
        uint32_t kk0 = keys.k0[0], kk1 = keys.k1[0];
        float2 z = make_float2(0.f, 0.f);
#pragma unroll 1
        for (int R = 0; R < 4; R++) {
            int r0 = 16 * R + g, r1 = r0 + 8;
            float2 c00 = *(float2*)&sm[LG_C + r0 * PL_ROW + cA];
            float2 c01 = *(float2*)&sm[LG_C + r0 * PL_ROW + cB];
            float2 c10 = *(float2*)&sm[LG_C + r1 * PL_ROW + cA];
            float2 c11 = *(float2*)&sm[LG_C + r1 * PL_ROW + cB];
            float2 n00 = elw2(0.f, 0.f, z, c00, tb + r0, cA, kk0, kk1, nscale);
            float2 n01 = elw2(0.f, 0.f, z, c01, tb + r0, cB, kk0, kk1, nscale);
            float2 n10 = elw2(0.f, 0.f, z, c10, tb + r1, cA, kk0, kk1, nscale);
            float2 n11 = elw2(0.f, 0.f, z, c11, tb + r1, cB, kk0, kk1, nscale);
            *(float2*)&sm[LG_XEX + r0 * PL_ROW + cA] = n00;
            *(float2*)&sm[LG_XEX + r0 * PL_ROW + cB] = n01;
            *(float2*)&sm[LG_XEX + r1 * PL_ROW + cA] = n10;
            *(float2*)&sm[LG_XEX + r1 * PL_ROW + cB] = n11;
            smu[LG_XT + r0 * XT_ROW + (cA & 3) * XT_CLS + (cA >> 2)] = f2tf32(n00.x);
            smu[LG_XT + r0 * XT_ROW + ((cA+1) & 3) * XT_CLS + ((cA+1) >> 2)] = f2tf32(n00.y);
            smu[LG_XT + r0 * XT_ROW + (cB & 3) * XT_CLS + (cB >> 2)] = f2tf32(n01.x);
            smu[LG_XT + r0 * XT_ROW + ((cB+1) & 3) * XT_CLS + ((cB+1) >> 2)] = f2tf32(n01.y);
            smu[LG_XT + r1 * XT_ROW + (cA & 3) * XT_CLS + (cA >> 2)] = f2tf32(n10.x);
            smu[LG_XT + r1 * XT_ROW + ((cA+1) & 3) * XT_CLS + ((cA+1) >> 2)] = f2tf32(n10.y);
            smu[LG_XT + r1 * XT_ROW + (cB & 3) * XT_CLS + (cB >> 2)] = f2tf32(n11.x);
            smu[LG_XT + r1 * XT_ROW + ((cB+1) & 3) * XT_CLS + ((cB+1) >> 2)] = f2tf32(n11.y);
        }
    }
    __syncthreads();

    // ---- steps 1..9: per pair (2 chunks = 32 rows): MMA reads, bar, writes ----
    for (int s = 1; s < STEPS; s++) {
        uint32_t kk0 = keys.k0[s], kk1 = keys.k1[s];
        bool lastS = (s == STEPS - 1);
#pragma unroll 1
        for (int P = 0; P < 2; P++) {
            float D[2][8];
#pragma unroll
            for (int c = 0; c < 2; c++) {
                int R = 2 * P + c;
                int r0 = 16 * R + g, r1 = r0 + 8;
                float D0[4] = {0,0,0,0}, D1[4] = {0,0,0,0};
                const uint32_t* xt0 = &smu[LG_XT + r0 * XT_ROW + i * XT_CLS];
                const uint32_t* xt1 = &smu[LG_XT + r1 * XT_ROW + i * XT_CLS];
#pragma unroll
                for (int j = 0; j < 8; j++) {
                    uint4 va = *(const uint4*)(xt0 + 4 * j);
                    uint4 vb = *(const uint4*)(xt1 + 4 * j);
                    uint32_t a[4];
                    a[0] = va.x; a[1] = vb.x; a[2] = va.y; a[3] = vb.y;
                    mma_tf32(D0, a, Bf[2 * j][0]);
                    mma_tf32(D1, a, Bf[2 * j][1]);
                    a[0] = va.z; a[1] = vb.z; a[2] = va.w; a[3] = vb.w;
                    mma_tf32(D0, a, Bf[2 * j + 1][0]);
                    mma_tf32(D1, a, Bf[2 * j + 1][1]);
                }
#pragma unroll
                for (int q = 0; q < 4; q++) { D[c][q] = D0[q]; D[c][4 + q] = D1[q]; }
            }
            __syncthreads();   // all pair-P XT reads done; safe to overwrite pair P
#pragma unroll
            for (int c = 0; c < 2; c++) {
                int R = 2 * P + c;
                int r0 = 16 * R + g, r1 = r0 + 8;
                float2 xo00 = *(float2*)&sm[LG_XEX + r0 * PL_ROW + cA];
                float2 xo01 = *(float2*)&sm[LG_XEX + r0 * PL_ROW + cB];
                float2 xo10 = *(float2*)&sm[LG_XEX + r1 * PL_ROW + cA];
                float2 xo11 = *(float2*)&sm[LG_XEX + r1 * PL_ROW + cB];
                float2 c00 = *(float2*)&sm[LG_C + r0 * PL_ROW + cA];
                float2 c01 = *(float2*)&sm[LG_C + r0 * PL_ROW + cB];
                float2 c10 = *(float2*)&sm[LG_C + r1 * PL_ROW + cA];
                float2 c11 = *(float2*)&sm[LG_C + r1 * PL_ROW + cB];
                float2 n00 = elw2(D[c][0], D[c][1], xo00, c00, tb + r0, cA, kk0, kk1, nscale);
                float2 n01 = elw2(D[c][4], D[c][5], xo01, c01, tb + r0, cB, kk0, kk1, nscale);
                float2 n10 = elw2(D[c][2], D[c][3], xo10, c10, tb + r1, cA, kk0, kk1, nscale);
                float2 n11 = elw2(D[c][6], D[c][7], xo11, c11, tb + r1, cB, kk0, kk1, nscale);
                *(float2*)&sm[LG_XEX + r0 * PL_ROW + cA] = n00;
                *(float2*)&sm[LG_XEX + r0 * PL_ROW + cB] = n01;
                *(float2*)&sm[LG_XEX + r1 * PL_ROW + cA] = n10;
                *(float2*)&sm[LG_XEX + r1 * PL_ROW + cB] = n11;
                if (!lastS) {
                    smu[LG_XT + r0 * XT_ROW + (cA & 3) * XT_CLS + (cA >> 2)] = f2tf32(n00.x);
                    smu[LG_XT + r0 * XT_ROW + ((cA+1) & 3) * XT_CLS + ((cA+1) >> 2)] = f2tf32(n00.y);
                    smu[LG_XT + r0 * XT_ROW + (cB & 3) * XT_CLS + (cB >> 2)] = f2tf32(n01.x);
                    smu[LG_XT + r0 * XT_ROW + ((cB+1) & 3) * XT_CLS + ((cB+1) >> 2)] = f2tf32(n01.y);
                    smu[LG_XT + r1 * XT_ROW + (cA & 3) * XT_CLS + (cA >> 2)] = f2tf32(n10.x);
                    smu[LG_XT + r1 * XT_ROW + ((cA+1) & 3) * XT_CLS + ((cA+1) >> 2)] = f2tf32(n10.y);
                    smu[LG_XT + r1 * XT_ROW + (cB & 3) * XT_CLS + (cB >> 2)] = f2tf32(n11.x);
                    smu[LG_XT + r1 * XT_ROW + ((cB+1) & 3) * XT_CLS + ((cB+1) >> 2)] = f2tf32(n11.y);
                }
            }
        }
    }
    __syncthreads();

    // output copy, coalesced
    float4* o4 = (float4*)(out + (size_t)tb * 128);
    for (int idx = tid; idx < 2048; idx += NTHREADS) {
        int r = idx >> 5, q = idx & 31;
        o4[idx] = *(float4*)&sm[LG_XEX + r * PL_ROW + 4 * q];
    }
}

// ===========================================================================
// Launch
// ===========================================================================
extern "C" void kernel_launch(void* const* d_in, const int* in_sizes, int n_in,
                              void* d_out, int out_size)
{
    const float* x_input = (const float*)d_in[0];
    const float* W       = (const float*)d_in[1];
    const float* J       = (const float*)d_in[2];
    const float* h       = (const float*)d_in[3];
    float* out           = (float*)d_out;

    Keys keys;
    for (int s = 0; s < STEPS; s++) {
        uint32_t o0, o1;
        threefry2x32_20(0u, 1u, 0u, (uint32_t)s, o0, o1);
        keys.k0[s] = o0;
        keys.k1[s] = o1;
    }

    static bool attr_set = false;
    if (!attr_set) {
        cudaFuncSetAttribute(phase1_mma,
            cudaFuncAttributeMaxDynamicSharedMemorySize, P1_SMEM);
        cudaFuncSetAttribute(langevin_mma,
            cudaFuncAttributeMaxDynamicSharedMemorySize, LG_SMEM);
        attr_set = true;
    }

    const int NT = B_ROWS / 64;   // 4096 tiles
    zero_kernel<<<1, 1>>>();
    phase1_mma<<<NT, NTHREADS, P1_SMEM>>>(x_input, W);
    finalize_kernel<<<1, 1>>>();
    langevin_mma<<<NT, NTHREADS, LG_SMEM>>>(x_input, J, h, out, keys);
}

// round 9
// speedup vs baseline: 1.9876x; 1.0490x over previous
#include <cuda_runtime.h>
#include <cstdint>
#include <math.h>

#define B_ROWS   262144
#define STEPS    10
#define NTHREADS 256

__device__ double g_sum;
__device__ float  g_noise_scale;

// ---- SMEM word-offset layouts (64-row tiles) ----
#define XT_ROW 164
#define XT_CLS 40
#define PL_ROW 132

#define LG_XT   0
#define LG_XEX  (64*XT_ROW)
#define LG_C    (LG_XEX + 64*PL_ROW)
#define LG_WORDS (LG_C + 64*PL_ROW)
#define LG_SMEM (LG_WORDS*4)

#define P1_XT  0
#define P1_XST (64*XT_ROW)
#define P1_WORDS (P1_XST + 64*PL_ROW)
#define P1_SMEM (P1_WORDS*4)

// ---------------------------------------------------------------------------
// mma.sync m16n8k8 tf32
// ---------------------------------------------------------------------------
__device__ __forceinline__ uint32_t f2tf32(float f) {
    uint32_t r;
    asm("cvt.rna.tf32.f32 %0, %1;" : "=r"(r) : "f"(f));
    return r;
}
__device__ __forceinline__ void mma_tf32(float d[4], const uint32_t a[4],
                                         const uint32_t b[2]) {
    asm volatile(
        "mma.sync.aligned.m16n8k8.row.col.f32.tf32.tf32.f32 "
        "{%0,%1,%2,%3}, {%4,%5,%6,%7}, {%8,%9}, {%0,%1,%2,%3};\n"
        : "+f"(d[0]), "+f"(d[1]), "+f"(d[2]), "+f"(d[3])
        : "r"(a[0]), "r"(a[1]), "r"(a[2]), "r"(a[3]), "r"(b[0]), "r"(b[1]));
}

__device__ __forceinline__ float tanh_fast(float x) {
    float r;
    asm("tanh.approx.f32 %0, %1;" : "=f"(r) : "f"(x));
    return r;
}

// mad.lo with runtime multiplier `one` (opaque 1) -> IMAD on the FMA pipe.
__device__ __forceinline__ uint32_t imad1(uint32_t a, uint32_t one, uint32_t b) {
    uint32_t r;
    asm("mad.lo.u32 %0, %1, %2, %3;" : "=r"(r) : "r"(a), "r"(one), "r"(b));
    return r;
}

// ---------------------------------------------------------------------------
// Threefry-2x32/20 — host version (key derivation)
// ---------------------------------------------------------------------------
__host__ __forceinline__ void threefry_host(
    uint32_t k0, uint32_t k1, uint32_t x0, uint32_t x1,
    uint32_t& o0, uint32_t& o1)
{
    uint32_t ks0 = k0, ks1 = k1, ks2 = k0 ^ k1 ^ 0x1BD11BDAu;
    x0 += ks0; x1 += ks1;
#define TF_R(r) { x0 += x1; x1 = (x1 << (r)) | (x1 >> (32 - (r))); x1 ^= x0; }
    TF_R(13) TF_R(15) TF_R(26) TF_R(6)
    x0 += ks1; x1 += ks2 + 1u;
    TF_R(17) TF_R(29) TF_R(16) TF_R(24)
    x0 += ks2; x1 += ks0 + 2u;
    TF_R(13) TF_R(15) TF_R(26) TF_R(6)
    x0 += ks0; x1 += ks1 + 3u;
    TF_R(17) TF_R(29) TF_R(16) TF_R(24)
    x0 += ks1; x1 += ks2 + 4u;
    TF_R(13) TF_R(15) TF_R(26) TF_R(6)
    x0 += ks2; x1 += ks0 + 5u;
#undef TF_R
    o0 = x0; o1 = x1;
}

// Device: pipe-balanced (x0-chain on IMAD/fma pipe, x1-chain on alu pipe).
// bits = o0 ^ o1, counter = (0, idx)  [partitionable scheme, round-4 verified]
__device__ __forceinline__ uint32_t rnd_bits(uint32_t one,
    uint32_t k0, uint32_t k1, uint32_t idx)
{
    uint32_t ks2 = k0 ^ k1 ^ 0x1BD11BDAu;
    uint32_t x0 = k0;            // 0 + ks0
    uint32_t x1 = idx + k1;      // idx + ks1
#define TF_B(r) { x0 = imad1(x0, one, x1); x1 = __funnelshift_l(x1, x1, r); x1 ^= x0; }
    TF_B(13) TF_B(15) TF_B(26) TF_B(6)
    x0 = imad1(x0, one, k1);  x1 += ks2 + 1u;
    TF_B(17) TF_B(29) TF_B(16) TF_B(24)
    x0 = imad1(x0, one, ks2); x1 += k0 + 2u;
    TF_B(13) TF_B(15) TF_B(26) TF_B(6)
    x0 = imad1(x0, one, k0);  x1 += k1 + 3u;
    TF_B(17) TF_B(29) TF_B(16) TF_B(24)
    x0 = imad1(x0, one, k1);  x1 += ks2 + 4u;
    TF_B(13) TF_B(15) TF_B(26) TF_B(6)
    x0 = imad1(x0, one, ks2); x1 += k0 + 5u;
#undef TF_B
    return x0 ^ x1;
}

__device__ __forceinline__ float bits_to_normal(uint32_t bits)
{
    const float lo = -0.99999994f;
    float u = __uint_as_float((bits >> 9) | 0x3f800000u) - 1.0f;
    float x = fmaf(u, 2.0f, lo);
    x = fmaxf(x, lo);
    float w = -__logf(fmaf(-x, x, 1.0f));
    float p;
    if (w < 5.0f) {
        w -= 2.5f;
        p = 2.81022636e-08f;
        p = fmaf(p, w, 3.43273939e-07f);
        p = fmaf(p, w, -3.5233877e-06f);
        p = fmaf(p, w, -4.39150654e-06f);
        p = fmaf(p, w, 0.00021858087f);
        p = fmaf(p, w, -0.00125372503f);
        p = fmaf(p, w, -0.00417768164f);
        p = fmaf(p, w, 0.246640727f);
        p = fmaf(p, w, 1.50140941f);
    } else {
        w = sqrtf(w) - 3.0f;
        p = -0.000200214257f;
        p = fmaf(p, w, 0.000100950558f);
        p = fmaf(p, w, 0.00134934322f);
        p = fmaf(p, w, -0.00367342844f);
        p = fmaf(p, w, 0.00573950773f);
        p = fmaf(p, w, -0.0076224613f);
        p = fmaf(p, w, 0.00943887047f);
        p = fmaf(p, w, 1.00167406f);
        p = fmaf(p, w, 2.83297682f);
    }
    return 1.41421354f * (p * x);
}

struct Keys { uint32_t k0[STEPS]; uint32_t k1[STEPS]; uint32_t one; };

__global__ void zero_kernel() { g_sum = 0.0; }
__global__ void finalize_kernel()
{
    double mean = g_sum * (1.0 / 33554432.0);
    float temp = 0.1f * (1.0f + (float)mean * 10.0f);
    g_noise_scale = sqrtf(2.0f * 0.1f * temp);
}

// x' = tanh((x + C) - 0.1*d + nscale*nrm)
__device__ __forceinline__ float2 elw2(uint32_t one, float d0, float d1,
    float2 xo, float2 cc, uint32_t row_g, uint32_t col0,
    uint32_t kk0, uint32_t kk1, float nscale)
{
    uint32_t base = row_g * 128u + col0;
    float n0 = bits_to_normal(rnd_bits(one, kk0, kk1, base));
    float n1 = bits_to_normal(rnd_bits(one, kk0, kk1, base + 1u));
    float2 r;
    r.x = tanh_fast(fmaf(n0, nscale, fmaf(d0, -0.1f, xo.x + cc.x)));
    r.y = tanh_fast(fmaf(n1, nscale, fmaf(d1, -0.1f, xo.y + cc.y)));
    return r;
}

// ===========================================================================
// Phase 1
// ===========================================================================
__global__ void __launch_bounds__(NTHREADS, 2) phase1_mma(
    const float* __restrict__ x_input, const float* __restrict__ W)
{
    extern __shared__ float sm[];
    uint32_t* smu = (uint32_t*)sm;
    int tid = threadIdx.x, w = tid >> 5, lane = tid & 31;
    int g = lane >> 2, i = lane & 3;
    int N0 = 16 * w;
    int tb = blockIdx.x * 64;

    const float4* W4 = (const float4*)W;
    for (int idx = tid; idx < 4096; idx += NTHREADS) {
        int r = idx >> 5, q = idx & 31;
        *(float4*)&sm[r * PL_ROW + 4 * q] = W4[idx];
    }
    __syncthreads();

    uint32_t Bf[16][2][2];
#pragma unroll
    for (int kk = 0; kk < 16; kk++)
#pragma unroll
        for (int j = 0; j < 2; j++) {
            Bf[kk][j][0] = f2tf32(sm[(8 * kk + i) * PL_ROW + N0 + 8 * j + g]);
            Bf[kk][j][1] = f2tf32(sm[(8 * kk + i + 4) * PL_ROW + N0 + 8 * j + g]);
        }
    __syncthreads();

    const float4* X4 = (const float4*)(x_input + (size_t)tb * 128);
    for (int idx = tid; idx < 2048; idx += NTHREADS) {
        int r = idx >> 5, q = idx & 31;
        float4 v = X4[idx];
        *(float4*)&sm[P1_XST + r * PL_ROW + 4 * q] = v;
        smu[P1_XT + r * XT_ROW + 0 * XT_CLS + q] = f2tf32(v.x);
        smu[P1_XT + r * XT_ROW + 1 * XT_CLS + q] = f2tf32(v.y);
        smu[P1_XT + r * XT_ROW + 2 * XT_CLS + q] = f2tf32(v.z);
        smu[P1_XT + r * XT_ROW + 3 * XT_CLS + q] = f2tf32(v.w);
    }
    __syncthreads();

    int cA = N0 + 2 * i, cB = cA + 8;
    float acc = 0.f;
#pragma unroll 1
    for (int R = 0; R < 4; R++) {
        int r0 = 16 * R + g, r1 = r0 + 8;
        float D0[4] = {0,0,0,0}, D1[4] = {0,0,0,0};
        const uint32_t* xt0 = &smu[P1_XT + r0 * XT_ROW + i * XT_CLS];
        const uint32_t* xt1 = &smu[P1_XT + r1 * XT_ROW + i * XT_CLS];
#pragma unroll
        for (int j = 0; j < 8; j++) {
            uint4 va = *(const uint4*)(xt0 + 4 * j);
            uint4 vb = *(const uint4*)(xt1 + 4 * j);
            uint32_t a[4];
            a[0] = va.x; a[1] = vb.x; a[2] = va.y; a[3] = vb.y;
            mma_tf32(D0, a, Bf[2 * j][0]);
            mma_tf32(D1, a, Bf[2 * j][1]);
            a[0] = va.z; a[1] = vb.z; a[2] = va.w; a[3] = vb.w;
            mma_tf32(D0, a, Bf[2 * j + 1][0]);
            mma_tf32(D1, a, Bf[2 * j + 1][1]);
        }
        float2 x00 = *(float2*)&sm[P1_XST + r0 * PL_ROW + cA];
        float2 x01 = *(float2*)&sm[P1_XST + r0 * PL_ROW + cB];
        float2 x10 = *(float2*)&sm[P1_XST + r1 * PL_ROW + cA];
        float2 x11 = *(float2*)&sm[P1_XST + r1 * PL_ROW + cB];
        float e;
        e = x00.x - tanh_fast(D0[0]); acc = fmaf(e, e, acc);
        e = x00.y - tanh_fast(D0[1]); acc = fmaf(e, e, acc);
        e = x01.x - tanh_fast(D1[0]); acc = fmaf(e, e, acc);
        e = x01.y - tanh_fast(D1[1]); acc = fmaf(e, e, acc);
        e = x10.x - tanh_fast(D0[2]); acc = fmaf(e, e, acc);
        e = x10.y - tanh_fast(D0[3]); acc = fmaf(e, e, acc);
        e = x11.x - tanh_fast(D1[2]); acc = fmaf(e, e, acc);
        e = x11.y - tanh_fast(D1[3]); acc = fmaf(e, e, acc);
    }
    double da = (double)acc;
#pragma unroll
    for (int off = 16; off; off >>= 1)
        da += __shfl_xor_sync(0xffffffffu, da, off);
    __shared__ double sacc[8];
    if (lane == 0) sacc[w] = da;
    __syncthreads();
    if (tid == 0) {
        double t = 0.0;
#pragma unroll
        for (int k = 0; k < 8; k++) t += sacc[k];
        atomicAdd(&g_sum, t);
    }
}

// ===========================================================================
// Langevin
// ===========================================================================
__global__ void __launch_bounds__(NTHREADS, 2) langevin_mma(
    const float* __restrict__ x_input, const float* __restrict__ J,
    const float* __restrict__ h, float* __restrict__ out, Keys keys)
{
    extern __shared__ float sm[];
    uint32_t* smu = (uint32_t*)sm;
    int tid = threadIdx.x, w = tid >> 5, lane = tid & 31;
    int g = lane >> 2, i = lane & 3;
    int N0 = 16 * w;
    int tb = blockIdx.x * 64;
    uint32_t one = keys.one;

    const float4* J4 = (const float4*)J;
    for (int idx = tid; idx < 4096; idx += NTHREADS) {
        int r = idx >> 5, q = idx & 31;
        *(float4*)&sm[r * PL_ROW + 4 * q] = J4[idx];
    }
    __syncthreads();

    uint32_t Bf[16][2][2];
#pragma unroll
    for (int kk = 0; kk < 16; kk++)
#pragma unroll
        for (int j = 0; j < 2; j++) {
            Bf[kk][j][0] = f2tf32(sm[(8 * kk + i) * PL_ROW + N0 + 8 * j + g]);
            Bf[kk][j][1] = f2tf32(sm[(8 * kk + i + 4) * PL_ROW + N0 + 8 * j + g]);
        }
    __syncthreads();

    const float4* X4 = (const float4*)(x_input + (size_t)tb * 128);
    const float4* H4 = (const float4*)h;
    for (int idx = tid; idx < 2048; idx += NTHREADS) {
        int r = idx >> 5, q = idx & 31;
        float4 v = X4[idx], hv = H4[q];
        float4 c;
        c.x = 0.1f * (v.x - hv.x);
        c.y = 0.1f * (v.y - hv.y);
        c.z = 0.1f * (v.z - hv.z);
        c.w = 0.1f * (v.w - hv.w);
        *(float4*)&sm[LG_C + r * PL_ROW + 4 * q] = c;
    }
    float nscale = g_noise_scale;
    __syncthreads();

    int cA = N0 + 2 * i, cB = cA + 8;

    // ---- step 0 ----
    {
        uint32_t kk0 = keys.k0[0], kk1 = keys.k1[0];
        float2 z = make_float2(0.f, 0.f);
#pragma unroll 1
        for (int R = 0; R < 4; R++) {
            int r0 = 16 * R + g, r1 = r0 + 8;
            float2 c00 = *(float2*)&sm[LG_C + r0 * PL_ROW + cA];
            float2 c01 = *(float2*)&sm[LG_C + r0 * PL_ROW + cB];
            float2 c10 = *(float2*)&sm[LG_C + r1 * PL_ROW + cA];
            float2 c11 = *(float2*)&sm[LG_C + r1 * PL_ROW + cB];
            float2 n00 = elw2(one, 0.f, 0.f, z, c00, tb + r0, cA, kk0, kk1, nscale);
            float2 n01 = elw2(one, 0.f, 0.f, z, c01, tb + r0, cB, kk0, kk1, nscale);
            float2 n10 = elw2(one, 0.f, 0.f, z, c10, tb + r1, cA, kk0, kk1, nscale);
            float2 n11 = elw2(one, 0.f, 0.f, z, c11, tb + r1, cB, kk0, kk1, nscale);
            *(float2*)&sm[LG_XEX + r0 * PL_ROW + cA] = n00;
            *(float2*)&sm[LG_XEX + r0 * PL_ROW + cB] = n01;
            *(float2*)&sm[LG_XEX + r1 * PL_ROW + cA] = n10;
            *(float2*)&sm[LG_XEX + r1 * PL_ROW + cB] = n11;
            smu[LG_XT + r0 * XT_ROW + (cA & 3) * XT_CLS + (cA >> 2)] = f2tf32(n00.x);
            smu[LG_XT + r0 * XT_ROW + ((cA+1) & 3) * XT_CLS + ((cA+1) >> 2)] = f2tf32(n00.y);
            smu[LG_XT + r0 * XT_ROW + (cB & 3) * XT_CLS + (cB >> 2)] = f2tf32(n01.x);
            smu[LG_XT + r0 * XT_ROW + ((cB+1) & 3) * XT_CLS + ((cB+1) >> 2)] = f2tf32(n01.y);
            smu[LG_XT + r1 * XT_ROW + (cA & 3) * XT_CLS + (cA >> 2)] = f2tf32(n10.x);
            smu[LG_XT + r1 * XT_ROW + ((cA+1) & 3) * XT_CLS + ((cA+1) >> 2)] = f2tf32(n10.y);
            smu[LG_XT + r1 * XT_ROW + (cB & 3) * XT_CLS + (cB >> 2)] = f2tf32(n11.x);
            smu[LG_XT + r1 * XT_ROW + ((cB+1) & 3) * XT_CLS + ((cB+1) >> 2)] = f2tf32(n11.y);
        }
    }
    __syncthreads();

    // ---- steps 1..9 ----
    for (int s = 1; s < STEPS; s++) {
        uint32_t kk0 = keys.k0[s], kk1 = keys.k1[s];
        bool lastS = (s == STEPS - 1);
#pragma unroll 1
        for (int P = 0; P < 2; P++) {
            float D[2][8];
#pragma unroll
            for (int c = 0; c < 2; c++) {
                int R = 2 * P + c;
                int r0 = 16 * R + g, r1 = r0 + 8;
                float D0[4] = {0,0,0,0}, D1[4] = {0,0,0,0};
                const uint32_t* xt0 = &smu[LG_XT + r0 * XT_ROW + i * XT_CLS];
                const uint32_t* xt1 = &smu[LG_XT + r1 * XT_ROW + i * XT_CLS];
#pragma unroll
                for (int j = 0; j < 8; j++) {
                    uint4 va = *(const uint4*)(xt0 + 4 * j);
                    uint4 vb = *(const uint4*)(xt1 + 4 * j);
                    uint32_t a[4];
                    a[0] = va.x; a[1] = vb.x; a[2] = va.y; a[3] = vb.y;
                    mma_tf32(D0, a, Bf[2 * j][0]);
                    mma_tf32(D1, a, Bf[2 * j][1]);
                    a[0] = va.z; a[1] = vb.z; a[2] = va.w; a[3] = vb.w;
                    mma_tf32(D0, a, Bf[2 * j + 1][0]);
                    mma_tf32(D1, a, Bf[2 * j + 1][1]);
                }
#pragma unroll
                for (int q = 0; q < 4; q++) { D[c][q] = D0[q]; D[c][4 + q] = D1[q]; }
            }
            __syncthreads();
#pragma unroll
            for (int c = 0; c < 2; c++) {
                int R = 2 * P + c;
                int r0 = 16 * R + g, r1 = r0 + 8;
                float2 xo00 = *(float2*)&sm[LG_XEX + r0 * PL_ROW + cA];
                float2 xo01 = *(float2*)&sm[LG_XEX + r0 * PL_ROW + cB];
                float2 xo10 = *(float2*)&sm[LG_XEX + r1 * PL_ROW + cA];
                float2 xo11 = *(float2*)&sm[LG_XEX + r1 * PL_ROW + cB];
                float2 c00 = *(float2*)&sm[LG_C + r0 * PL_ROW + cA];
                float2 c01 = *(float2*)&sm[LG_C + r0 * PL_ROW + cB];
                float2 c10 = *(float2*)&sm[LG_C + r1 * PL_ROW + cA];
                float2 c11 = *(float2*)&sm[LG_C + r1 * PL_ROW + cB];
                float2 n00 = elw2(one, D[c][0], D[c][1], xo00, c00, tb + r0, cA, kk0, kk1, nscale);
                float2 n01 = elw2(one, D[c][4], D[c][5], xo01, c01, tb + r0, cB, kk0, kk1, nscale);
                float2 n10 = elw2(one, D[c][2], D[c][3], xo10, c10, tb + r1, cA, kk0, kk1, nscale);
                float2 n11 = elw2(one, D[c][6], D[c][7], xo11, c11, tb + r1, cB, kk0, kk1, nscale);
                *(float2*)&sm[LG_XEX + r0 * PL_ROW + cA] = n00;
                *(float2*)&sm[LG_XEX + r0 * PL_ROW + cB] = n01;
                *(float2*)&sm[LG_XEX + r1 * PL_ROW + cA] = n10;
                *(float2*)&sm[LG_XEX + r1 * PL_ROW + cB] = n11;
                if (!lastS) {
                    smu[LG_XT + r0 * XT_ROW + (cA & 3) * XT_CLS + (cA >> 2)] = f2tf32(n00.x);
                    smu[LG_XT + r0 * XT_ROW + ((cA+1) & 3) * XT_CLS + ((cA+1) >> 2)] = f2tf32(n00.y);
                    smu[LG_XT + r0 * XT_ROW + (cB & 3) * XT_CLS + (cB >> 2)] = f2tf32(n01.x);
                    smu[LG_XT + r0 * XT_ROW + ((cB+1) & 3) * XT_CLS + ((cB+1) >> 2)] = f2tf32(n01.y);
                    smu[LG_XT + r1 * XT_ROW + (cA & 3) * XT_CLS + (cA >> 2)] = f2tf32(n10.x);
                    smu[LG_XT + r1 * XT_ROW + ((cA+1) & 3) * XT_CLS + ((cA+1) >> 2)] = f2tf32(n10.y);
                    smu[LG_XT + r1 * XT_ROW + (cB & 3) * XT_CLS + (cB >> 2)] = f2tf32(n11.x);
                    smu[LG_XT + r1 * XT_ROW + ((cB+1) & 3) * XT_CLS + ((cB+1) >> 2)] = f2tf32(n11.y);
                }
            }
        }
    }
    __syncthreads();

    float4* o4 = (float4*)(out + (size_t)tb * 128);
    for (int idx = tid; idx < 2048; idx += NTHREADS) {
        int r = idx >> 5, q = idx & 31;
        o4[idx] = *(float4*)&sm[LG_XEX + r * PL_ROW + 4 * q];
    }
}

// ===========================================================================
// Launch
// ===========================================================================
extern "C" void kernel_launch(void* const* d_in, const int* in_sizes, int n_in,
                              void* d_out, int out_size)
{
    const float* x_input = (const float*)d_in[0];
    const float* W       = (const float*)d_in[1];
    const float* J       = (const float*)d_in[2];
    const float* h       = (const float*)d_in[3];
    float* out           = (float*)d_out;

    Keys keys;
    for (int s = 0; s < STEPS; s++) {
        uint32_t o0, o1;
        threefry_host(0u, 1u, 0u, (uint32_t)s, o0, o1);
        keys.k0[s] = o0;
        keys.k1[s] = o1;
    }
    keys.one = 1u;

    static bool attr_set = false;
    if (!attr_set) {
        cudaFuncSetAttribute(phase1_mma,
            cudaFuncAttributeMaxDynamicSharedMemorySize, P1_SMEM);
        cudaFuncSetAttribute(langevin_mma,
            cudaFuncAttributeMaxDynamicSharedMemorySize, LG_SMEM);
        attr_set = true;
    }

    const int NT = B_ROWS / 64;
    zero_kernel<<<1, 1>>>();
    phase1_mma<<<NT, NTHREADS, P1_SMEM>>>(x_input, W);
    finalize_kernel<<<1, 1>>>();
    langevin_mma<<<NT, NTHREADS, LG_SMEM>>>(x_input, J, h, out, keys);
}

// round 10
// speedup vs baseline: 2.1405x; 1.0769x over previous
#include <cuda_runtime.h>
#include <cstdint>
#include <math.h>

#define B_ROWS   262144
#define STEPS    10
#define NTHREADS 256

__device__ double g_sum;
__device__ float  g_noise_scale;

// ---- phase1 SMEM layout (unchanged from passing round) ----
#define XT_ROW 164
#define XT_CLS 40
#define PL_ROW 132
#define P1_XT  0
#define P1_XST (64*XT_ROW)
#define P1_WORDS (P1_XST + 64*PL_ROW)
#define P1_SMEM (P1_WORDS*4)

// ---- langevin SMEM layout (words) ----
// XT bf16 state, double buffered. Class layout: word w (=col/2, 0..63):
// class = w&3 (== lane's i), sub s = w>>2 (0..15).
// addr = row*ROWP + class*CSP + s.  CSP=20, ROWP=80 chosen so the 8-lane
// LDS.128 phases hit disjoint 16B bank-groups (g-set {4,1,6,3} vs i-set {0,5,2,7}).
#define CSP  20
#define ROWP 80
#define XTB  (64*ROWP)          // 5120 words per buffer
#define LG_XT0 0
#define LG_XT1 XTB
#define LG_SH  (2*XTB)          // shared region: J staging (128*132=16896 w),
#define LG_XEX LG_SH            //   then reused as XEX (64*132)
#define LG_C   (LG_SH + 64*PL_ROW) //   and C (64*132)
#define LG_WORDS (LG_SH + 16896)
#define LG_SMEM (LG_WORDS*4)    // 108544 B -> 2 CTAs/SM

// ---------------------------------------------------------------------------
// MMA helpers
// ---------------------------------------------------------------------------
__device__ __forceinline__ uint32_t f2tf32(float f) {
    uint32_t r;
    asm("cvt.rna.tf32.f32 %0, %1;" : "=r"(r) : "f"(f));
    return r;
}
__device__ __forceinline__ void mma_tf32(float d[4], const uint32_t a[4],
                                         const uint32_t b[2]) {
    asm volatile(
        "mma.sync.aligned.m16n8k8.row.col.f32.tf32.tf32.f32 "
        "{%0,%1,%2,%3}, {%4,%5,%6,%7}, {%8,%9}, {%0,%1,%2,%3};\n"
        : "+f"(d[0]), "+f"(d[1]), "+f"(d[2]), "+f"(d[3])
        : "r"(a[0]), "r"(a[1]), "r"(a[2]), "r"(a[3]), "r"(b[0]), "r"(b[1]));
}
__device__ __forceinline__ void mma_bf16(float d[4], const uint32_t a[4],
                                         const uint32_t b[2]) {
    asm volatile(
        "mma.sync.aligned.m16n8k16.row.col.f32.bf16.bf16.f32 "
        "{%0,%1,%2,%3}, {%4,%5,%6,%7}, {%8,%9}, {%0,%1,%2,%3};\n"
        : "+f"(d[0]), "+f"(d[1]), "+f"(d[2]), "+f"(d[3])
        : "r"(a[0]), "r"(a[1]), "r"(a[2]), "r"(a[3]), "r"(b[0]), "r"(b[1]));
}
// pack {hi<<16 | lo} bf16x2
__device__ __forceinline__ uint32_t pack_bf16(float hi, float lo) {
    uint32_t r;
    asm("cvt.rn.bf16x2.f32 %0, %1, %2;" : "=r"(r) : "f"(hi), "f"(lo));
    return r;
}
__device__ __forceinline__ float tanh_fast(float x) {
    float r;
    asm("tanh.approx.f32 %0, %1;" : "=f"(r) : "f"(x));
    return r;
}
__device__ __forceinline__ uint32_t imad1(uint32_t a, uint32_t one, uint32_t b) {
    uint32_t r;
    asm("mad.lo.u32 %0, %1, %2, %3;" : "=r"(r) : "r"(a), "r"(one), "r"(b));
    return r;
}

// ---------------------------------------------------------------------------
// Threefry-2x32/20
// ---------------------------------------------------------------------------
__host__ __forceinline__ void threefry_host(
    uint32_t k0, uint32_t k1, uint32_t x0, uint32_t x1,
    uint32_t& o0, uint32_t& o1)
{
    uint32_t ks0 = k0, ks1 = k1, ks2 = k0 ^ k1 ^ 0x1BD11BDAu;
    x0 += ks0; x1 += ks1;
#define TF_R(r) { x0 += x1; x1 = (x1 << (r)) | (x1 >> (32 - (r))); x1 ^= x0; }
    TF_R(13) TF_R(15) TF_R(26) TF_R(6)
    x0 += ks1; x1 += ks2 + 1u;
    TF_R(17) TF_R(29) TF_R(16) TF_R(24)
    x0 += ks2; x1 += ks0 + 2u;
    TF_R(13) TF_R(15) TF_R(26) TF_R(6)
    x0 += ks0; x1 += ks1 + 3u;
    TF_R(17) TF_R(29) TF_R(16) TF_R(24)
    x0 += ks1; x1 += ks2 + 4u;
    TF_R(13) TF_R(15) TF_R(26) TF_R(6)
    x0 += ks2; x1 += ks0 + 5u;
#undef TF_R
    o0 = x0; o1 = x1;
}

__device__ __forceinline__ uint32_t rnd_bits(uint32_t one,
    uint32_t k0, uint32_t k1, uint32_t idx)
{
    uint32_t ks2 = k0 ^ k1 ^ 0x1BD11BDAu;
    uint32_t x0 = k0;
    uint32_t x1 = idx + k1;
#define TF_B(r) { x0 = imad1(x0, one, x1); x1 = __funnelshift_l(x1, x1, r); x1 ^= x0; }
    TF_B(13) TF_B(15) TF_B(26) TF_B(6)
    x0 = imad1(x0, one, k1);  x1 += ks2 + 1u;
    TF_B(17) TF_B(29) TF_B(16) TF_B(24)
    x0 = imad1(x0, one, ks2); x1 += k0 + 2u;
    TF_B(13) TF_B(15) TF_B(26) TF_B(6)
    x0 = imad1(x0, one, k0);  x1 += k1 + 3u;
    TF_B(17) TF_B(29) TF_B(16) TF_B(24)
    x0 = imad1(x0, one, k1);  x1 += ks2 + 4u;
    TF_B(13) TF_B(15) TF_B(26) TF_B(6)
    x0 = imad1(x0, one, ks2); x1 += k0 + 5u;
#undef TF_B
    return x0 ^ x1;
}

__device__ __forceinline__ float bits_to_normal(uint32_t bits)
{
    const float lo = -0.99999994f;
    float u = __uint_as_float((bits >> 9) | 0x3f800000u) - 1.0f;
    float x = fmaf(u, 2.0f, lo);
    x = fmaxf(x, lo);
    float w = -__logf(fmaf(-x, x, 1.0f));
    float p;
    if (w < 5.0f) {
        w -= 2.5f;
        p = 2.81022636e-08f;
        p = fmaf(p, w, 3.43273939e-07f);
        p = fmaf(p, w, -3.5233877e-06f);
        p = fmaf(p, w, -4.39150654e-06f);
        p = fmaf(p, w, 0.00021858087f);
        p = fmaf(p, w, -0.00125372503f);
        p = fmaf(p, w, -0.00417768164f);
        p = fmaf(p, w, 0.246640727f);
        p = fmaf(p, w, 1.50140941f);
    } else {
        w = sqrtf(w) - 3.0f;
        p = -0.000200214257f;
        p = fmaf(p, w, 0.000100950558f);
        p = fmaf(p, w, 0.00134934322f);
        p = fmaf(p, w, -0.00367342844f);
        p = fmaf(p, w, 0.00573950773f);
        p = fmaf(p, w, -0.0076224613f);
        p = fmaf(p, w, 0.00943887047f);
        p = fmaf(p, w, 1.00167406f);
        p = fmaf(p, w, 2.83297682f);
    }
    return 1.41421354f * (p * x);
}

struct Keys { uint32_t k0[STEPS]; uint32_t k1[STEPS]; uint32_t one; };

__global__ void zero_kernel() { g_sum = 0.0; }
__global__ void finalize_kernel()
{
    double mean = g_sum * (1.0 / 33554432.0);
    float temp = 0.1f * (1.0f + (float)mean * 10.0f);
    g_noise_scale = sqrtf(2.0f * 0.1f * temp);
}

__device__ __forceinline__ float2 elw2(uint32_t one, float d0, float d1,
    float2 xo, float2 cc, uint32_t row_g, uint32_t col0,
    uint32_t kk0, uint32_t kk1, float nscale)
{
    uint32_t base = row_g * 128u + col0;
    float n0 = bits_to_normal(rnd_bits(one, kk0, kk1, base));
    float n1 = bits_to_normal(rnd_bits(one, kk0, kk1, base + 1u));
    float2 r;
    r.x = tanh_fast(fmaf(n0, nscale, fmaf(d0, -0.1f, xo.x + cc.x)));
    r.y = tanh_fast(fmaf(n1, nscale, fmaf(d1, -0.1f, xo.y + cc.y)));
    return r;
}

// ===========================================================================
// Phase 1 (unchanged, tf32 — passed round 9)
// ===========================================================================
__global__ void __launch_bounds__(NTHREADS, 2) phase1_mma(
    const float* __restrict__ x_input, const float* __restrict__ W)
{
    extern __shared__ float sm[];
    uint32_t* smu = (uint32_t*)sm;
    int tid = threadIdx.x, w = tid >> 5, lane = tid & 31;
    int g = lane >> 2, i = lane & 3;
    int N0 = 16 * w;
    int tb = blockIdx.x * 64;

    const float4* W4 = (const float4*)W;
    for (int idx = tid; idx < 4096; idx += NTHREADS) {
        int r = idx >> 5, q = idx & 31;
        *(float4*)&sm[r * PL_ROW + 4 * q] = W4[idx];
    }
    __syncthreads();

    uint32_t Bf[16][2][2];
#pragma unroll
    for (int kk = 0; kk < 16; kk++)
#pragma unroll
        for (int j = 0; j < 2; j++) {
            Bf[kk][j][0] = f2tf32(sm[(8 * kk + i) * PL_ROW + N0 + 8 * j + g]);
            Bf[kk][j][1] = f2tf32(sm[(8 * kk + i + 4) * PL_ROW + N0 + 8 * j + g]);
        }
    __syncthreads();

    const float4* X4 = (const float4*)(x_input + (size_t)tb * 128);
    for (int idx = tid; idx < 2048; idx += NTHREADS) {
        int r = idx >> 5, q = idx & 31;
        float4 v = X4[idx];
        *(float4*)&sm[P1_XST + r * PL_ROW + 4 * q] = v;
        smu[P1_XT + r * XT_ROW + 0 * XT_CLS + q] = f2tf32(v.x);
        smu[P1_XT + r * XT_ROW + 1 * XT_CLS + q] = f2tf32(v.y);
        smu[P1_XT + r * XT_ROW + 2 * XT_CLS + q] = f2tf32(v.z);
        smu[P1_XT + r * XT_ROW + 3 * XT_CLS + q] = f2tf32(v.w);
    }
    __syncthreads();

    int cA = N0 + 2 * i, cB = cA + 8;
    float acc = 0.f;
#pragma unroll 1
    for (int R = 0; R < 4; R++) {
        int r0 = 16 * R + g, r1 = r0 + 8;
        float D0[4] = {0,0,0,0}, D1[4] = {0,0,0,0};
        const uint32_t* xt0 = &smu[P1_XT + r0 * XT_ROW + i * XT_CLS];
        const uint32_t* xt1 = &smu[P1_XT + r1 * XT_ROW + i * XT_CLS];
#pragma unroll
        for (int j = 0; j < 8; j++) {
            uint4 va = *(const uint4*)(xt0 + 4 * j);
            uint4 vb = *(const uint4*)(xt1 + 4 * j);
            uint32_t a[4];
            a[0] = va.x; a[1] = vb.x; a[2] = va.y; a[3] = vb.y;
            mma_tf32(D0, a, Bf[2 * j][0]);
            mma_tf32(D1, a, Bf[2 * j][1]);
            a[0] = va.z; a[1] = vb.z; a[2] = va.w; a[3] = vb.w;
            mma_tf32(D0, a, Bf[2 * j + 1][0]);
            mma_tf32(D1, a, Bf[2 * j + 1][1]);
        }
        float2 x00 = *(float2*)&sm[P1_XST + r0 * PL_ROW + cA];
        float2 x01 = *(float2*)&sm[P1_XST + r0 * PL_ROW + cB];
        float2 x10 = *(float2*)&sm[P1_XST + r1 * PL_ROW + cA];
        float2 x11 = *(float2*)&sm[P1_XST + r1 * PL_ROW + cB];
        float e;
        e = x00.x - tanh_fast(D0[0]); acc = fmaf(e, e, acc);
        e = x00.y - tanh_fast(D0[1]); acc = fmaf(e, e, acc);
        e = x01.x - tanh_fast(D1[0]); acc = fmaf(e, e, acc);
        e = x01.y - tanh_fast(D1[1]); acc = fmaf(e, e, acc);
        e = x10.x - tanh_fast(D0[2]); acc = fmaf(e, e, acc);
        e = x10.y - tanh_fast(D0[3]); acc = fmaf(e, e, acc);
        e = x11.x - tanh_fast(D1[2]); acc = fmaf(e, e, acc);
        e = x11.y - tanh_fast(D1[3]); acc = fmaf(e, e, acc);
    }
    double da = (double)acc;
#pragma unroll
    for (int off = 16; off; off >>= 1)
        da += __shfl_xor_sync(0xffffffffu, da, off);
    __shared__ double sacc[8];
    if (lane == 0) sacc[w] = da;
    __syncthreads();
    if (tid == 0) {
        double t = 0.0;
#pragma unroll
        for (int k = 0; k < 8; k++) t += sacc[k];
        atomicAdd(&g_sum, t);
    }
}

// ===========================================================================
// Langevin: bf16 MMA, double-buffered XT, ONE barrier per step
// ===========================================================================
__global__ void __launch_bounds__(NTHREADS, 2) langevin_bf16(
    const float* __restrict__ x_input, const float* __restrict__ J,
    const float* __restrict__ h, float* __restrict__ out, Keys keys)
{
    extern __shared__ float sm[];
    uint32_t* smu = (uint32_t*)sm;
    int tid = threadIdx.x, w = tid >> 5, lane = tid & 31;
    int g = lane >> 2, i = lane & 3;
    int N0 = 16 * w;
    int tb = blockIdx.x * 64;
    uint32_t one = keys.one;

    // stage J [128x128] into shared region (row stride 132)
    const float4* J4 = (const float4*)J;
    for (int idx = tid; idx < 4096; idx += NTHREADS) {
        int r = idx >> 5, q = idx & 31;
        *(float4*)&sm[LG_SH + r * PL_ROW + 4 * q] = J4[idx];
    }
    __syncthreads();

    // persistent bf16 B fragments (m16n8k16, col-major B = J[k][n]):
    // Bf[kk][j][0] = {J[16kk+2i+1][c] : J[16kk+2i][c]},  c = N0+8j+g
    // Bf[kk][j][1] = {J[16kk+2i+9][c] : J[16kk+2i+8][c]}
    uint32_t Bf[8][2][2];
#pragma unroll
    for (int kk = 0; kk < 8; kk++)
#pragma unroll
        for (int j = 0; j < 2; j++) {
            int c = N0 + 8 * j + g;
            int k0r = 16 * kk + 2 * i;
            float j0 = sm[LG_SH + (k0r    ) * PL_ROW + c];
            float j1 = sm[LG_SH + (k0r + 1) * PL_ROW + c];
            float j2 = sm[LG_SH + (k0r + 8) * PL_ROW + c];
            float j3 = sm[LG_SH + (k0r + 9) * PL_ROW + c];
            Bf[kk][j][0] = pack_bf16(j1, j0);
            Bf[kk][j][1] = pack_bf16(j3, j2);
        }
    __syncthreads();

    // C = 0.1*(xin - h), overwrites part of J staging region
    const float4* X4 = (const float4*)(x_input + (size_t)tb * 128);
    const float4* H4 = (const float4*)h;
    for (int idx = tid; idx < 2048; idx += NTHREADS) {
        int r = idx >> 5, q = idx & 31;
        float4 v = X4[idx], hv = H4[q];
        float4 c;
        c.x = 0.1f * (v.x - hv.x);
        c.y = 0.1f * (v.y - hv.y);
        c.z = 0.1f * (v.z - hv.z);
        c.w = 0.1f * (v.w - hv.w);
        *(float4*)&sm[LG_C + r * PL_ROW + 4 * q] = c;
    }
    float nscale = g_noise_scale;
    __syncthreads();

    int cA = N0 + 2 * i, cB = cA + 8;
    // XT slots this thread writes: class i, sub-index sA (cA pair), sB (cB pair)
    int sA = 2 * w, sB = 2 * w + 1;
    int xbase = CSP * i;

    // ---- step 0: x = 0, d = 0; writes XEX + XT buffer 0 ----
    {
        uint32_t kk0 = keys.k0[0], kk1 = keys.k1[0];
        float2 z = make_float2(0.f, 0.f);
#pragma unroll
        for (int R = 0; R < 4; R++) {
            int r0 = 16 * R + g, r1 = r0 + 8;
            float2 c00 = *(float2*)&sm[LG_C + r0 * PL_ROW + cA];
            float2 c01 = *(float2*)&sm[LG_C + r0 * PL_ROW + cB];
            float2 c10 = *(float2*)&sm[LG_C + r1 * PL_ROW + cA];
            float2 c11 = *(float2*)&sm[LG_C + r1 * PL_ROW + cB];
            float2 n00 = elw2(one, 0.f, 0.f, z, c00, tb + r0, cA, kk0, kk1, nscale);
            float2 n01 = elw2(one, 0.f, 0.f, z, c01, tb + r0, cB, kk0, kk1, nscale);
            float2 n10 = elw2(one, 0.f, 0.f, z, c10, tb + r1, cA, kk0, kk1, nscale);
            float2 n11 = elw2(one, 0.f, 0.f, z, c11, tb + r1, cB, kk0, kk1, nscale);
            *(float2*)&sm[LG_XEX + r0 * PL_ROW + cA] = n00;
            *(float2*)&sm[LG_XEX + r0 * PL_ROW + cB] = n01;
            *(float2*)&sm[LG_XEX + r1 * PL_ROW + cA] = n10;
            *(float2*)&sm[LG_XEX + r1 * PL_ROW + cB] = n11;
            smu[LG_XT0 + r0 * ROWP + xbase + sA] = pack_bf16(n00.y, n00.x);
            smu[LG_XT0 + r0 * ROWP + xbase + sB] = pack_bf16(n01.y, n01.x);
            smu[LG_XT0 + r1 * ROWP + xbase + sA] = pack_bf16(n10.y, n10.x);
            smu[LG_XT0 + r1 * ROWP + xbase + sB] = pack_bf16(n11.y, n11.x);
        }
    }
    __syncthreads();

    // ---- steps 1..9: read XT[(s-1)&1], write XT[s&1]; 1 barrier/step ----
#pragma unroll 1
    for (int s = 1; s < STEPS; s++) {
        uint32_t kk0 = keys.k0[s], kk1 = keys.k1[s];
        bool lastS = (s == STEPS - 1);
        int xtR = ((s - 1) & 1) ? LG_XT1 : LG_XT0;
        int xtW = (s & 1) ? LG_XT1 : LG_XT0;
#pragma unroll
        for (int R = 0; R < 4; R++) {
            int r0 = 16 * R + g, r1 = r0 + 8;
            float D0[4] = {0,0,0,0}, D1[4] = {0,0,0,0};
            const uint32_t* xt0 = &smu[xtR + r0 * ROWP + xbase];
            const uint32_t* xt1 = &smu[xtR + r1 * ROWP + xbase];
#pragma unroll
            for (int j = 0; j < 4; j++) {
                uint4 va = *(const uint4*)(xt0 + 4 * j);
                uint4 vb = *(const uint4*)(xt1 + 4 * j);
                uint32_t a[4];
                a[0] = va.x; a[1] = vb.x; a[2] = va.y; a[3] = vb.y;
                mma_bf16(D0, a, Bf[2 * j][0]);
                mma_bf16(D1, a, Bf[2 * j][1]);
                a[0] = va.z; a[1] = vb.z; a[2] = va.w; a[3] = vb.w;
                mma_bf16(D0, a, Bf[2 * j + 1][0]);
                mma_bf16(D1, a, Bf[2 * j + 1][1]);
            }
            float2 xo00 = *(float2*)&sm[LG_XEX + r0 * PL_ROW + cA];
            float2 xo01 = *(float2*)&sm[LG_XEX + r0 * PL_ROW + cB];
            float2 xo10 = *(float2*)&sm[LG_XEX + r1 * PL_ROW + cA];
            float2 xo11 = *(float2*)&sm[LG_XEX + r1 * PL_ROW + cB];
            float2 c00 = *(float2*)&sm[LG_C + r0 * PL_ROW + cA];
            float2 c01 = *(float2*)&sm[LG_C + r0 * PL_ROW + cB];
            float2 c10 = *(float2*)&sm[LG_C + r1 * PL_ROW + cA];
            float2 c11 = *(float2*)&sm[LG_C + r1 * PL_ROW + cB];
            float2 n00 = elw2(one, D0[0], D0[1], xo00, c00, tb + r0, cA, kk0, kk1, nscale);
            float2 n01 = elw2(one, D1[0], D1[1], xo01, c01, tb + r0, cB, kk0, kk1, nscale);
            float2 n10 = elw2(one, D0[2], D0[3], xo10, c10, tb + r1, cA, kk0, kk1, nscale);
            float2 n11 = elw2(one, D1[2], D1[3], xo11, c11, tb + r1, cB, kk0, kk1, nscale);
            *(float2*)&sm[LG_XEX + r0 * PL_ROW + cA] = n00;
            *(float2*)&sm[LG_XEX + r0 * PL_ROW + cB] = n01;
            *(float2*)&sm[LG_XEX + r1 * PL_ROW + cA] = n10;
            *(float2*)&sm[LG_XEX + r1 * PL_ROW + cB] = n11;
            if (!lastS) {
                smu[xtW + r0 * ROWP + xbase + sA] = pack_bf16(n00.y, n00.x);
                smu[xtW + r0 * ROWP + xbase + sB] = pack_bf16(n01.y, n01.x);
                smu[xtW + r1 * ROWP + xbase + sA] = pack_bf16(n10.y, n10.x);
                smu[xtW + r1 * ROWP + xbase + sB] = pack_bf16(n11.y, n11.x);
            }
        }
        __syncthreads();
    }

    // output copy, coalesced
    float4* o4 = (float4*)(out + (size_t)tb * 128);
    for (int idx = tid; idx < 2048; idx += NTHREADS) {
        int r = idx >> 5, q = idx & 31;
        o4[idx] = *(float4*)&sm[LG_XEX + r * PL_ROW + 4 * q];
    }
}

// ===========================================================================
// Launch
// ===========================================================================
extern "C" void kernel_launch(void* const* d_in, const int* in_sizes, int n_in,
                              void* d_out, int out_size)
{
    const float* x_input = (const float*)d_in[0];
    const float* W       = (const float*)d_in[1];
    const float* J       = (const float*)d_in[2];
    const float* h       = (const float*)d_in[3];
    float* out           = (float*)d_out;

    Keys keys;
    for (int s = 0; s < STEPS; s++) {
        uint32_t o0, o1;
        threefry_host(0u, 1u, 0u, (uint32_t)s, o0, o1);
        keys.k0[s] = o0;
        keys.k1[s] = o1;
    }
    keys.one = 1u;

    static bool attr_set = false;
    if (!attr_set) {
        cudaFuncSetAttribute(phase1_mma,
            cudaFuncAttributeMaxDynamicSharedMemorySize, P1_SMEM);
        cudaFuncSetAttribute(langevin_bf16,
            cudaFuncAttributeMaxDynamicSharedMemorySize, LG_SMEM);
        attr_set = true;
    }

    const int NT = B_ROWS / 64;
    zero_kernel<<<1, 1>>>();
    phase1_mma<<<NT, NTHREADS, P1_SMEM>>>(x_input, W);
    finalize_kernel<<<1, 1>>>();
    langevin_bf16<<<NT, NTHREADS, LG_SMEM>>>(x_input, J, h, out, keys);
}